// round 11
// baseline (speedup 1.0000x reference)
#include <cuda_runtime.h>
#include <cuda_bf16.h>
#include <cstdint>
#include <cstddef>

#define T_DEC 32
#define T_CTX 32
#define BSZ   128
#define EDIM  1024
#define HDIM  1024
#define CDIM  1024
#define G4    4096   // 4*H
#define K2    2048   // [hi|lo] split storage

// ---------------- scratch (static device globals) ----------------
__device__ __nv_bfloat16 g_embs[T_DEC * BSZ * K2];
__device__ __nv_bfloat16 g_Wihs[G4 * K2];
__device__ __nv_bfloat16 g_Whhs[G4 * K2];
__device__ __nv_bfloat16 g_Wqs [HDIM * K2];
__device__ __nv_bfloat16 g_Wks [HDIM * K2];
__device__ __nv_bfloat16 g_ctxs[T_CTX * BSZ * K2];
__device__ __nv_bfloat16 g_rnns[T_DEC * BSZ * K2];
__device__ float g_xp   [T_DEC * BSZ * G4];
__device__ float g_q    [T_DEC * BSZ * HDIM];
__device__ float g_k    [T_CTX * BSZ * HDIM];
__device__ float g_c    [BSZ * HDIM];
__device__ float g_attn [BSZ * T_DEC * T_CTX];
__device__ float g_bias [G4];
__device__ float g_vn   [HDIM];
__device__ unsigned g_xp_done[T_DEC];        // xp per-timestep completion (64 blocks each)
__device__ unsigned g_rnn_done[T_DEC * 2];   // rnn per-(t, bgroup) completion (64 blocks each)

// ---------------- helpers ----------------
__device__ __forceinline__ float tanh_fast(float x) {
    float r; asm("tanh.approx.f32 %0, %1;" : "=f"(r) : "f"(x)); return r;
}
__device__ __forceinline__ float sigm(float x) { return 1.0f / (1.0f + __expf(-x)); }

__device__ __forceinline__ void split2(float x, __nv_bfloat16& h, __nv_bfloat16& l) {
    h = __float2bfloat16_rn(x);
    l = __float2bfloat16_rn(x - __bfloat162float(h));
}

__device__ __forceinline__ void cp16(uint32_t dst, const void* src) {
    asm volatile("cp.async.cg.shared.global [%0], [%1], 16;" :: "r"(dst), "l"(src) : "memory");
}
__device__ __forceinline__ void cp_commit() {
    asm volatile("cp.async.commit_group;" ::: "memory");
}
__device__ __forceinline__ void cp_wait0() {
    asm volatile("cp.async.wait_group 0;" ::: "memory");
}
__device__ __forceinline__ void cp_wait1() {
    asm volatile("cp.async.wait_group 1;" ::: "memory");
}
__device__ __forceinline__ unsigned ld_acq(const unsigned* p) {
    unsigned v;
    asm volatile("ld.acquire.gpu.u32 %0, [%1];" : "=r"(v) : "l"(p) : "memory");
    return v;
}

#define LDMX4(d0,d1,d2,d3,addr) \
    asm volatile("ldmatrix.sync.aligned.m8n8.x4.shared.b16 {%0,%1,%2,%3}, [%4];" \
                 : "=r"(d0), "=r"(d1), "=r"(d2), "=r"(d3) : "r"(addr))

#define MMA16816(acc, a, b0, b1) \
    asm volatile("mma.sync.aligned.m16n8k16.row.col.f32.bf16.bf16.f32 " \
                 "{%0,%1,%2,%3}, {%4,%5,%6,%7}, {%8,%9}, {%0,%1,%2,%3};" \
                 : "+f"((acc)[0]), "+f"((acc)[1]), "+f"((acc)[2]), "+f"((acc)[3]) \
                 : "r"((a)[0]), "r"((a)[1]), "r"((a)[2]), "r"((a)[3]), "r"(b0), "r"(b1))

// ---------------- init: bias sum + zero c + flag reset ----------------
__global__ void init_kernel(const float* __restrict__ b_ih, const float* __restrict__ b_hh) {
    int i = blockIdx.x * blockDim.x + threadIdx.x;
    if (i < BSZ * HDIM) g_c[i] = 0.0f;
    if (i < G4) g_bias[i] = b_ih[i] + b_hh[i];
    if (i < T_DEC) g_xp_done[i] = 0;
    if (i < T_DEC * 2) g_rnn_done[i] = 0;
}

// ---------------- vn = norm_scalar * v / ||v|| ----------------
__global__ void vn_kernel(const float* __restrict__ v, const float* __restrict__ ns) {
    __shared__ float red[256];
    float s = 0.0f;
    for (int i = threadIdx.x; i < HDIM; i += 256) { float x = v[i]; s += x * x; }
    red[threadIdx.x] = s;
    __syncthreads();
    for (int off = 128; off > 0; off >>= 1) {
        if (threadIdx.x < off) red[threadIdx.x] += red[threadIdx.x + off];
        __syncthreads();
    }
    float inv = ns[0] * rsqrtf(red[0]);
    for (int i = threadIdx.x; i < HDIM; i += 256) g_vn[i] = v[i] * inv;
}

// ---------------- embedding gather + 2-chunk split ----------------
__global__ void embed_split(const int* __restrict__ tokens, const float* __restrict__ table) {
    int tb = blockIdx.x;
    int tok = tokens[tb];
    size_t base = (size_t)tb * K2;
#pragma unroll
    for (int j = 0; j < 4; j++) {
        int k = threadIdx.x + j * 256;
        float x = table[(size_t)tok * EDIM + k];
        __nv_bfloat16 h, l; split2(x, h, l);
        g_embs[base + k] = h;
        g_embs[base + EDIM + k] = l;
    }
}

// ---------------- fp32 -> [hi|lo] split ----------------
__global__ void split2_kernel(const float* __restrict__ X, __nv_bfloat16* __restrict__ Y,
                              int K, int total) {
    int idx = blockIdx.x * 256 + threadIdx.x;
    if (idx >= total) return;
    int m = idx / K, k = idx - m * K;
    float x = X[idx];
    __nv_bfloat16 h, l; split2(x, h, l);
    size_t base = (size_t)m * 2 * K;
    Y[base + k] = h;
    Y[base + K + k] = l;
}

// ============================================================================
// Triple-pass split GEMM, 2-stage ring, 2 CTAs/SM (R8/R10-proven config).
// done[y]++ after epilogue (optional); waits on rnn_done pair for y (optional).
// ============================================================================
template<int BM, int BN, int WM, int WN, int NT>
__global__ __launch_bounds__(NT, 2) void gemm3(
    const __nv_bfloat16* __restrict__ A, const __nv_bfloat16* __restrict__ B,
    float* __restrict__ C, int M, int N, int K,
    unsigned* done, const unsigned* waitPair)
{
    constexpr int NWN = BN / WN;
    constexpr int MI  = WM / 16;
    constexpr int NJ  = WN / 8;
    constexpr int NLD = WN / 16;
    constexpr int ANUM = BM * 16 / NT;
    constexpr int BNUM = BN * 16 / NT;
    constexpr int SS = 2 * BM * 128 + 2 * BN * 128;

    extern __shared__ __align__(16) unsigned char smem_raw[];
    uint32_t asB = (uint32_t)__cvta_generic_to_shared(smem_raw);

    const int tid  = threadIdx.x;
    const int lane = tid & 31;
    const int w    = tid >> 5;
    const int wm   = w / NWN, wn = w % NWN;
    const int mBase = blockIdx.y * BM;
    const int nBase = blockIdx.x * BN;
    const int Kr = 2 * K;

    // optional producer wait: A rows for this y must be published
    if (waitPair) {
        if (tid == 0) {
            const unsigned* p0 = waitPair + 2 * blockIdx.y;
            while (ld_acq(p0) < 64u || ld_acq(p0 + 1) < 64u) __nanosleep(128);
        }
        __syncthreads();
    }

    float acc[MI][NJ][4];
#pragma unroll
    for (int i = 0; i < MI; i++)
#pragma unroll
        for (int j = 0; j < NJ; j++)
#pragma unroll
            for (int r = 0; r < 4; r++) acc[i][j][r] = 0.0f;

    const int s = lane & 7;
    const int rowA0 = wm * WM + (lane & 7) + ((lane >> 3) & 1) * 8;
    const int cA    = (lane >> 4);
    const int rowB0 = wn * WN + (lane & 7) + ((lane & 16) ? 8 : 0);
    const int cB    = (lane >> 3) & 1;

    const int kIters = K / 64;

    auto issue = [&](int kc, int st) {
        uint32_t sbase = asB + st * SS;
#pragma unroll
        for (int i = 0; i < ANUM; i++) {
            int idx = tid + i * NT;
            int half = idx >= BM * 8 ? 1 : 0;
            int rem = idx - half * BM * 8;
            int r = rem >> 3, c = rem & 7;
            cp16(sbase + half * (BM * 128) + r * 128 + ((c ^ (r & 7)) << 4),
                 A + (size_t)(mBase + r) * Kr + half * K + kc * 64 + c * 8);
        }
        uint32_t bbase = sbase + 2 * BM * 128;
#pragma unroll
        for (int i = 0; i < BNUM; i++) {
            int idx = tid + i * NT;
            int half = idx >= BN * 8 ? 1 : 0;
            int rem = idx - half * BN * 8;
            int r = rem >> 3, c = rem & 7;
            cp16(bbase + half * (BN * 128) + r * 128 + ((c ^ (r & 7)) << 4),
                 B + (size_t)(nBase + r) * Kr + half * K + kc * 64 + c * 8);
        }
        cp_commit();
    };

    issue(0, 0);
    issue(1, 1);

    for (int kc = 0; kc < kIters; kc++) {
        int st = kc & 1;
        if (kc + 1 < kIters) cp_wait1(); else cp_wait0();
        __syncthreads();

        uint32_t aH = asB + st * SS;
        uint32_t aL = aH + BM * 128;
        uint32_t bH = aH + 2 * BM * 128;
        uint32_t bL = bH + BN * 128;

#pragma unroll
        for (int kk = 0; kk < 4; kk++) {
            uint32_t ofA = (((kk * 2 + cA) ^ s) << 4);
            uint32_t ofB = (((kk * 2 + cB) ^ s) << 4);
            uint32_t ahf[MI][4], alf[MI][4];
#pragma unroll
            for (int i = 0; i < MI; i++) {
                int row = rowA0 + i * 16;
                LDMX4(ahf[i][0], ahf[i][1], ahf[i][2], ahf[i][3], aH + row * 128 + ofA);
                LDMX4(alf[i][0], alf[i][1], alf[i][2], alf[i][3], aL + row * 128 + ofA);
            }
            uint32_t bhf[NLD][4], blf[NLD][4];
#pragma unroll
            for (int j = 0; j < NLD; j++) {
                int row = rowB0 + j * 16;
                LDMX4(bhf[j][0], bhf[j][1], bhf[j][2], bhf[j][3], bH + row * 128 + ofB);
                LDMX4(blf[j][0], blf[j][1], blf[j][2], blf[j][3], bL + row * 128 + ofB);
            }
#pragma unroll
            for (int i = 0; i < MI; i++)
#pragma unroll
                for (int j = 0; j < NJ; j++)
                    MMA16816(acc[i][j], ahf[i], bhf[j >> 1][(j & 1) * 2], bhf[j >> 1][(j & 1) * 2 + 1]);
#pragma unroll
            for (int i = 0; i < MI; i++)
#pragma unroll
                for (int j = 0; j < NJ; j++)
                    MMA16816(acc[i][j], alf[i], bhf[j >> 1][(j & 1) * 2], bhf[j >> 1][(j & 1) * 2 + 1]);
#pragma unroll
            for (int i = 0; i < MI; i++)
#pragma unroll
                for (int j = 0; j < NJ; j++)
                    MMA16816(acc[i][j], ahf[i], blf[j >> 1][(j & 1) * 2], blf[j >> 1][(j & 1) * 2 + 1]);
        }

        if (kc + 2 < kIters) {
            __syncthreads();            // all warps done reading slot st
            issue(kc + 2, st);
        }
    }

#pragma unroll
    for (int i = 0; i < MI; i++) {
        int row = mBase + wm * WM + i * 16 + (lane >> 2);
#pragma unroll
        for (int j = 0; j < NJ; j++) {
            int col = nBase + wn * WN + j * 8 + (lane & 3) * 2;
            *(float2*)(C + (size_t)row * N + col)       = make_float2(acc[i][j][0], acc[i][j][1]);
            *(float2*)(C + (size_t)(row + 8) * N + col) = make_float2(acc[i][j][2], acc[i][j][3]);
        }
    }

    if (done) {
        __threadfence();
        __syncthreads();
        if (tid == 0) atomicAdd(&done[blockIdx.y], 1u);
    }
}

// ---------------- persistent LSTM: per-(t,bgroup) flag sync, xp-flag pacing --
__global__ __launch_bounds__(256) void lstm_persistent(
    const __nv_bfloat16* __restrict__ Whhs, float* __restrict__ rnn_out)
{
    constexpr int BM = 64, BN = 64, WM = 32, WN = 16, NT = 256;
    constexpr int NWN = BN / WN;      // 4
    constexpr int MI = WM / 16;       // 2
    constexpr int NJ = WN / 8;        // 2
    constexpr int ANUM = BM * 16 / NT;// 4
    constexpr int BNUM = BN * 16 / NT;// 4
    constexpr int SS = 2 * BM * 128 + 2 * BN * 128;   // 32KB
    constexpr int K = 1024;
    constexpr unsigned XP_BLOCKS_PER_T = 64;

    extern __shared__ __align__(16) unsigned char smem_raw[];
    uint32_t asB = (uint32_t)__cvta_generic_to_shared(smem_raw);
    float* gsh = (float*)smem_raw;

    const int tid  = threadIdx.x;
    const int lane = tid & 31;
    const int w    = tid >> 5;
    const int wm   = w / NWN, wn = w % NWN;
    const int u0   = blockIdx.x * 16;
    const int b0   = blockIdx.y * 64;
    const int bg   = blockIdx.y;      // b-group 0/1

    const int s = lane & 7;
    const int rowA0 = wm * WM + (lane & 7) + ((lane >> 3) & 1) * 8;
    const int cA    = (lane >> 4);
    const int rowB0 = wn * WN + (lane & 7) + ((lane & 16) ? 8 : 0);
    const int cB    = (lane >> 3) & 1;

    int aHalf[ANUM], aR[ANUM], aC[ANUM];
    int bHalf[BNUM], bGrow[BNUM], bR[BNUM], bC[BNUM];
#pragma unroll
    for (int i = 0; i < ANUM; i++) {
        int idx = tid + i * NT;
        aHalf[i] = idx >= BM * 8 ? 1 : 0;
        int rem = idx - aHalf[i] * BM * 8;
        aR[i] = rem >> 3; aC[i] = rem & 7;
    }
#pragma unroll
    for (int i = 0; i < BNUM; i++) {
        int idx = tid + i * NT;
        bHalf[i] = idx >= BN * 8 ? 1 : 0;
        int rem = idx - bHalf[i] * BN * 8;
        bR[i] = rem >> 3; bC[i] = rem & 7;
        bGrow[i] = (bR[i] >> 4) * HDIM + u0 + (bR[i] & 15);   // gate*H + u
    }

    for (int t = 0; t < T_DEC; t++) {
        float acc[MI][NJ][4];
#pragma unroll
        for (int i = 0; i < MI; i++)
#pragma unroll
            for (int j = 0; j < NJ; j++)
#pragma unroll
                for (int r = 0; r < 4; r++) acc[i][j][r] = 0.0f;

        if (t > 0) {
            // wait for own b-group of rnn[t-1] (64 u-blocks)
            if (tid == 0) {
                const unsigned* p = &g_rnn_done[(t - 1) * 2 + bg];
                while (ld_acq(p) < 64u) __nanosleep(64);
            }
            __syncthreads();

            const __nv_bfloat16* hprev = g_rnns + (size_t)(t - 1) * BSZ * K2;
            auto issue = [&](int kc, int st) {
                uint32_t sbase = asB + st * SS;
#pragma unroll
                for (int i = 0; i < ANUM; i++)
                    cp16(sbase + aHalf[i] * (BM * 128) + aR[i] * 128 + ((aC[i] ^ (aR[i] & 7)) << 4),
                         hprev + (size_t)(b0 + aR[i]) * K2 + aHalf[i] * K + kc * 64 + aC[i] * 8);
                uint32_t bbase = sbase + 2 * BM * 128;
#pragma unroll
                for (int i = 0; i < BNUM; i++)
                    cp16(bbase + bHalf[i] * (BN * 128) + bR[i] * 128 + ((bC[i] ^ (bR[i] & 7)) << 4),
                         Whhs + (size_t)bGrow[i] * K2 + bHalf[i] * K + kc * 64 + bC[i] * 8);
                cp_commit();
            };

            issue(0, 0);
            issue(1, 1);

            const int kIters = K / 64;   // 16
            for (int kc = 0; kc < kIters; kc++) {
                int st = kc % 3;
                if (kc + 1 < kIters) cp_wait1(); else cp_wait0();
                __syncthreads();
                if (kc + 2 < kIters) issue(kc + 2, (kc + 2) % 3);

                uint32_t aH = asB + st * SS;
                uint32_t aL = aH + BM * 128;
                uint32_t bH = aH + 2 * BM * 128;
                uint32_t bL = bH + BN * 128;

#pragma unroll
                for (int kk = 0; kk < 4; kk++) {
                    uint32_t ofA = (((kk * 2 + cA) ^ s) << 4);
                    uint32_t ofB = (((kk * 2 + cB) ^ s) << 4);
                    uint32_t ahf[MI][4], alf[MI][4];
#pragma unroll
                    for (int i = 0; i < MI; i++) {
                        int row = rowA0 + i * 16;
                        LDMX4(ahf[i][0], ahf[i][1], ahf[i][2], ahf[i][3], aH + row * 128 + ofA);
                        LDMX4(alf[i][0], alf[i][1], alf[i][2], alf[i][3], aL + row * 128 + ofA);
                    }
                    uint32_t bhf[4], blf[4];
                    LDMX4(bhf[0], bhf[1], bhf[2], bhf[3], bH + rowB0 * 128 + ofB);
                    LDMX4(blf[0], blf[1], blf[2], blf[3], bL + rowB0 * 128 + ofB);
#pragma unroll
                    for (int i = 0; i < MI; i++)
#pragma unroll
                        for (int j = 0; j < NJ; j++)
                            MMA16816(acc[i][j], ahf[i], bhf[j * 2], bhf[j * 2 + 1]);
#pragma unroll
                    for (int i = 0; i < MI; i++)
#pragma unroll
                        for (int j = 0; j < NJ; j++)
                            MMA16816(acc[i][j], alf[i], bhf[j * 2], bhf[j * 2 + 1]);
#pragma unroll
                    for (int i = 0; i < MI; i++)
#pragma unroll
                        for (int j = 0; j < NJ; j++)
                            MMA16816(acc[i][j], ahf[i], blf[j * 2], blf[j * 2 + 1]);
                }
            }
            __syncthreads();   // all warps done reading stages before gsh aliases them
        } else {
            __syncthreads();
        }

        // stage gates in smem (aliases mainloop buffers)
#pragma unroll
        for (int i = 0; i < MI; i++) {
            int m = wm * WM + i * 16 + (lane >> 2);
#pragma unroll
            for (int j = 0; j < NJ; j++) {
                int col = wn * WN + j * 8 + (lane & 3) * 2;
                gsh[m * 65 + col]           = acc[i][j][0];
                gsh[m * 65 + col + 1]       = acc[i][j][1];
                gsh[(m + 8) * 65 + col]     = acc[i][j][2];
                gsh[(m + 8) * 65 + col + 1] = acc[i][j][3];
            }
        }
        __syncthreads();

        // wait for xp[t] (xp GEMM runs concurrently on another stream)
        if (tid == 0) {
            const unsigned* p = &g_xp_done[t];
            while (ld_acq(p) < XP_BLOCKS_PER_T) __nanosleep(128);
        }
        __syncthreads();

        // fused cell update for the 64b x 16u tile
#pragma unroll
        for (int sIt = 0; sIt < 4; sIt++) {
            int idx = tid + sIt * 256;
            int bl = idx >> 4, uu = idx & 15;
            int b = b0 + bl, u = u0 + uu;
            size_t xb = ((size_t)t * BSZ + b) * G4 + u;
            float gi = gsh[bl * 65 + uu]      + g_bias[u]            + g_xp[xb];
            float gf = gsh[bl * 65 + 16 + uu] + g_bias[u + HDIM]     + g_xp[xb + HDIM];
            float gg = gsh[bl * 65 + 32 + uu] + g_bias[u + 2 * HDIM] + g_xp[xb + 2 * HDIM];
            float go = gsh[bl * 65 + 48 + uu] + g_bias[u + 3 * HDIM] + g_xp[xb + 3 * HDIM];
            float cp = g_c[(size_t)b * HDIM + u];
            float c  = sigm(gf) * cp + sigm(gi) * tanhf(gg);
            float h  = sigm(go) * tanhf(c);
            g_c[(size_t)b * HDIM + u] = c;
            rnn_out[((size_t)t * BSZ + b) * HDIM + u] = h;
            __nv_bfloat16 hh, hl; split2(h, hh, hl);
            size_t rb2 = ((size_t)t * BSZ + b) * K2;
            g_rnns[rb2 + u] = hh;
            g_rnns[rb2 + HDIM + u] = hl;
        }

        // publish rnn[t] for this b-group (consumed by next step + q GEMM)
        __threadfence();
        __syncthreads();
        if (tid == 0) atomicAdd(&g_rnn_done[t * 2 + bg], 1u);
    }
}

// ---------------- attention scores + masked softmax (4 tq per block) --------
__global__ __launch_bounds__(256) void scores_kernel(const int* __restrict__ ctx_len,
                                                     const float* __restrict__ att_bias) {
    int tq0 = blockIdx.x * 4, b = blockIdx.y;
    __shared__ float qsh[4][HDIM];
    __shared__ float vnsh[HDIM];
    __shared__ float ssh[4][T_CTX];

    for (int i = threadIdx.x; i < 4 * HDIM; i += 256) {
        int tqi = i >> 10, u = i & 1023;
        qsh[tqi][u] = g_q[((size_t)(tq0 + tqi) * BSZ + b) * HDIM + u] + att_bias[u];
    }
    for (int i = threadIdx.x; i < HDIM; i += 256) vnsh[i] = g_vn[i];
    __syncthreads();

    int w = threadIdx.x >> 5, lane = threadIdx.x & 31;
#pragma unroll
    for (int tkk = 0; tkk < 4; tkk++) {
        int tk = tkk * 8 + w;
        const float* krow = g_k + ((size_t)tk * BSZ + b) * HDIM;
        float s0 = 0.f, s1 = 0.f, s2 = 0.f, s3 = 0.f;
        for (int u = lane; u < HDIM; u += 32) {
            float kv = krow[u], vn = vnsh[u];
            s0 += tanh_fast(qsh[0][u] + kv) * vn;
            s1 += tanh_fast(qsh[1][u] + kv) * vn;
            s2 += tanh_fast(qsh[2][u] + kv) * vn;
            s3 += tanh_fast(qsh[3][u] + kv) * vn;
        }
#pragma unroll
        for (int off = 16; off > 0; off >>= 1) {
            s0 += __shfl_xor_sync(0xffffffffu, s0, off);
            s1 += __shfl_xor_sync(0xffffffffu, s1, off);
            s2 += __shfl_xor_sync(0xffffffffu, s2, off);
            s3 += __shfl_xor_sync(0xffffffffu, s3, off);
        }
        if (lane == 0) { ssh[0][tk] = s0; ssh[1][tk] = s1; ssh[2][tk] = s2; ssh[3][tk] = s3; }
    }
    __syncthreads();

    if (threadIdx.x < 128) {
        int tqi = threadIdx.x >> 5;
        float s = ssh[tqi][lane];
        if (lane >= ctx_len[b]) s = -65504.0f;
        float m = s;
#pragma unroll
        for (int off = 16; off > 0; off >>= 1)
            m = fmaxf(m, __shfl_xor_sync(0xffffffffu, m, off));
        float e = __expf(s - m);
        float sum = e;
#pragma unroll
        for (int off = 16; off > 0; off >>= 1)
            sum += __shfl_xor_sync(0xffffffffu, sum, off);
        g_attn[((size_t)b * T_DEC + tq0 + tqi) * T_CTX + lane] = e / sum;
    }
}

// ---------------- attn_out: 16 tq per block, context read once --------------
__global__ __launch_bounds__(256) void attnctx_kernel(
    const float* __restrict__ context, float* __restrict__ attn_out)
{
    int tqh = blockIdx.x * 16, b = blockIdx.y;
    __shared__ float wsh[16][32];
#pragma unroll
    for (int it = 0; it < 2; it++) {
        int i = threadIdx.x + it * 256;
        if (i < 512) {
            int tq = i >> 5, tk = i & 31;
            wsh[tq][tk] = g_attn[((size_t)b * T_DEC + tqh + tq) * T_CTX + tk];
        }
    }
    __syncthreads();

    int c4 = threadIdx.x;
    float acc[16][4];
#pragma unroll
    for (int tq = 0; tq < 16; tq++)
#pragma unroll
        for (int r = 0; r < 4; r++) acc[tq][r] = 0.0f;

#pragma unroll 4
    for (int tk = 0; tk < T_CTX; tk++) {
        float4 v = *(const float4*)(context + ((size_t)tk * BSZ + b) * CDIM + c4 * 4);
#pragma unroll
        for (int tq = 0; tq < 16; tq++) {
            float wt = wsh[tq][tk];
            acc[tq][0] = fmaf(wt, v.x, acc[tq][0]);
            acc[tq][1] = fmaf(wt, v.y, acc[tq][1]);
            acc[tq][2] = fmaf(wt, v.z, acc[tq][2]);
            acc[tq][3] = fmaf(wt, v.w, acc[tq][3]);
        }
    }
#pragma unroll
    for (int tq = 0; tq < 16; tq++)
        *(float4*)(attn_out + ((size_t)(tqh + tq) * BSZ + b) * CDIM + c4 * 4) =
            make_float4(acc[tq][0], acc[tq][1], acc[tq][2], acc[tq][3]);
}

// ---------------- launcher ----------------
extern "C" void kernel_launch(void* const* d_in, const int* in_sizes, int n_in,
                              void* d_out, int out_size)
{
    const int*   ctx_len     = (const int*)  d_in[0];
    const int*   tokens      = (const int*)  d_in[1];
    const float* context     = (const float*)d_in[2];
    const float* emb_table   = (const float*)d_in[3];
    const float* W_ih        = (const float*)d_in[4];
    const float* W_hh        = (const float*)d_in[5];
    const float* b_ih        = (const float*)d_in[6];
    const float* b_hh        = (const float*)d_in[7];
    const float* Wq          = (const float*)d_in[8];
    const float* Wk          = (const float*)d_in[9];
    const float* v_att       = (const float*)d_in[10];
    const float* att_bias    = (const float*)d_in[11];
    const float* norm_scalar = (const float*)d_in[12];

    float* attn_out = (float*)d_out;
    float* rnn_out  = attn_out + (size_t)T_DEC * BSZ * CDIM;

    __nv_bfloat16 *p_embs, *p_Wihs, *p_Whhs, *p_Wqs, *p_Wks, *p_ctxs, *p_rnns;
    float *p_xp, *p_q, *p_k;
    unsigned *p_xpdone, *p_rnndone;
    cudaGetSymbolAddress((void**)&p_embs, g_embs);
    cudaGetSymbolAddress((void**)&p_Wihs, g_Wihs);
    cudaGetSymbolAddress((void**)&p_Whhs, g_Whhs);
    cudaGetSymbolAddress((void**)&p_Wqs,  g_Wqs);
    cudaGetSymbolAddress((void**)&p_Wks,  g_Wks);
    cudaGetSymbolAddress((void**)&p_ctxs, g_ctxs);
    cudaGetSymbolAddress((void**)&p_rnns, g_rnns);
    cudaGetSymbolAddress((void**)&p_xp,   g_xp);
    cudaGetSymbolAddress((void**)&p_q,    g_q);
    cudaGetSymbolAddress((void**)&p_k,    g_k);
    cudaGetSymbolAddress((void**)&p_xpdone,  g_xp_done);
    cudaGetSymbolAddress((void**)&p_rnndone, g_rnn_done);

    static cudaStream_t s2 = nullptr, s3 = nullptr;
    static cudaEvent_t evFork = nullptr, evJoin = nullptr, evWhh = nullptr, evLstm = nullptr;
    if (!s2) {
        cudaStreamCreateWithFlags(&s2, cudaStreamNonBlocking);
        cudaStreamCreateWithFlags(&s3, cudaStreamNonBlocking);
        cudaEventCreateWithFlags(&evFork, cudaEventDisableTiming);
        cudaEventCreateWithFlags(&evJoin, cudaEventDisableTiming);
        cudaEventCreateWithFlags(&evWhh,  cudaEventDisableTiming);
        cudaEventCreateWithFlags(&evLstm, cudaEventDisableTiming);
    }

    const int GEMM_SMEM = 2 * (2 * 128 * 128 + 2 * 64 * 128);   // 96KB -> 2 CTAs/SM
    cudaFuncSetAttribute(gemm3<128, 64, 32, 32, 256>,
                         cudaFuncAttributeMaxDynamicSharedMemorySize, GEMM_SMEM);
    const int LSTM_SMEM = 3 * (2 * 64 * 128 + 2 * 64 * 128);    // 96KB
    cudaFuncSetAttribute(lstm_persistent,
                         cudaFuncAttributeMaxDynamicSharedMemorySize, LSTM_SMEM);

    // fork side stream s2 into capture
    cudaEventRecord(evFork, 0);
    cudaStreamWaitEvent(s2, evFork, 0);

    // ---- s2: k-projection path (independent of LSTM) ----
    split2_kernel<<<(HDIM * HDIM + 255) / 256, 256, 0, s2>>>(Wq, p_Wqs, HDIM, HDIM * HDIM);
    split2_kernel<<<(HDIM * CDIM + 255) / 256, 256, 0, s2>>>(Wk, p_Wks, CDIM, HDIM * CDIM);
    split2_kernel<<<(T_CTX * BSZ * CDIM + 255) / 256, 256, 0, s2>>>(
        context, p_ctxs, CDIM, T_CTX * BSZ * CDIM);
    gemm3<128, 64, 32, 32, 256>
        <<<dim3(HDIM / 64, (T_CTX * BSZ) / 128), 256, GEMM_SMEM, s2>>>(
        p_ctxs, p_Wks, p_k, T_CTX * BSZ, HDIM, CDIM, nullptr, nullptr);
    cudaEventRecord(evJoin, s2);

    // ---- main stream: prep ----
    init_kernel<<<(BSZ * HDIM + 255) / 256, 256>>>(b_ih, b_hh);
    vn_kernel<<<1, 256>>>(v_att, norm_scalar);
    embed_split<<<T_DEC * BSZ, 256>>>(tokens, emb_table);
    split2_kernel<<<(G4 * EDIM + 255) / 256, 256>>>(W_ih, p_Wihs, EDIM, G4 * EDIM);
    split2_kernel<<<(G4 * HDIM + 255) / 256, 256>>>(W_hh, p_Whhs, HDIM, G4 * HDIM);
    cudaEventRecord(evWhh, 0);   // deps for LSTM: init flags + bias + Whh split

    // ---- s3: persistent LSTM, self-paced on xp flags, CONCURRENT with xp ----
    cudaStreamWaitEvent(s3, evWhh, 0);
    lstm_persistent<<<dim3(HDIM / 16, BSZ / 64), 256, LSTM_SMEM, s3>>>(p_Whhs, rnn_out);
    cudaEventRecord(evLstm, s3);

    // ---- main stream: xp GEMM with per-t completion flags ----
    gemm3<128, 64, 32, 32, 256>
        <<<dim3(G4 / 64, (T_DEC * BSZ) / 128), 256, GEMM_SMEM>>>(
        p_embs, p_Wihs, p_xp, T_DEC * BSZ, G4, EDIM, p_xpdone, nullptr);

    // ---- main stream: q GEMM, self-paced on rnn_done flags (overlaps LSTM) ----
    gemm3<128, 64, 32, 32, 256>
        <<<dim3(HDIM / 64, (T_DEC * BSZ) / 128), 256, GEMM_SMEM>>>(
        p_rnns, p_Wqs, p_q, T_DEC * BSZ, HDIM, HDIM, nullptr, p_rnndone);

    // join LSTM (rnn_out is part of d_out) + k-path, then attention
    cudaStreamWaitEvent(0, evLstm, 0);
    cudaStreamWaitEvent(0, evJoin, 0);

    scores_kernel<<<dim3(T_DEC / 4, BSZ), 256>>>(ctx_len, att_bias);
    attnctx_kernel<<<dim3(2, BSZ), 256>>>(context, attn_out);
}

// round 12
// speedup vs baseline: 1.2761x; 1.2761x over previous
#include <cuda_runtime.h>
#include <cuda_bf16.h>
#include <cstdint>
#include <cstddef>

#define T_DEC 32
#define T_CTX 32
#define BSZ   128
#define EDIM  1024
#define HDIM  1024
#define CDIM  1024
#define G4    4096   // 4*H
#define K2    2048   // [hi|lo] split storage

// ---------------- scratch (static device globals) ----------------
__device__ __nv_bfloat16 g_embs[T_DEC * BSZ * K2];
__device__ __nv_bfloat16 g_Wihs[G4 * K2];
__device__ __nv_bfloat16 g_Whhs[G4 * K2];
__device__ __nv_bfloat16 g_Wqs [HDIM * K2];
__device__ __nv_bfloat16 g_Wks [HDIM * K2];
__device__ __nv_bfloat16 g_ctxs[T_CTX * BSZ * K2];
__device__ __nv_bfloat16 g_rnns[T_DEC * BSZ * K2];
__device__ float g_xp   [T_DEC * BSZ * G4];
__device__ float g_q    [T_DEC * BSZ * HDIM];
__device__ float g_k    [T_CTX * BSZ * HDIM];
__device__ float g_c    [BSZ * HDIM];
__device__ float g_attn [BSZ * T_DEC * T_CTX];
__device__ float g_bias [G4];
__device__ float g_vn   [HDIM];
__device__ unsigned g_bar_cnt;
__device__ unsigned g_bar_gen;
__device__ unsigned g_xp_done[T_DEC];   // per-timestep xp completion counters

// ---------------- helpers ----------------
__device__ __forceinline__ float tanh_fast(float x) {
    float r; asm("tanh.approx.f32 %0, %1;" : "=f"(r) : "f"(x)); return r;
}
__device__ __forceinline__ float sigm(float x) { return 1.0f / (1.0f + __expf(-x)); }

__device__ __forceinline__ void split2(float x, __nv_bfloat16& h, __nv_bfloat16& l) {
    h = __float2bfloat16_rn(x);
    l = __float2bfloat16_rn(x - __bfloat162float(h));
}

__device__ __forceinline__ void cp16(uint32_t dst, const void* src) {
    asm volatile("cp.async.cg.shared.global [%0], [%1], 16;" :: "r"(dst), "l"(src) : "memory");
}
__device__ __forceinline__ void cp_commit() {
    asm volatile("cp.async.commit_group;" ::: "memory");
}
__device__ __forceinline__ void cp_wait0() {
    asm volatile("cp.async.wait_group 0;" ::: "memory");
}
__device__ __forceinline__ void cp_wait1() {
    asm volatile("cp.async.wait_group 1;" ::: "memory");
}

#define LDMX4(d0,d1,d2,d3,addr) \
    asm volatile("ldmatrix.sync.aligned.m8n8.x4.shared.b16 {%0,%1,%2,%3}, [%4];" \
                 : "=r"(d0), "=r"(d1), "=r"(d2), "=r"(d3) : "r"(addr))

#define MMA16816(acc, a, b0, b1) \
    asm volatile("mma.sync.aligned.m16n8k16.row.col.f32.bf16.bf16.f32 " \
                 "{%0,%1,%2,%3}, {%4,%5,%6,%7}, {%8,%9}, {%0,%1,%2,%3};" \
                 : "+f"((acc)[0]), "+f"((acc)[1]), "+f"((acc)[2]), "+f"((acc)[3]) \
                 : "r"((a)[0]), "r"((a)[1]), "r"((a)[2]), "r"((a)[3]), "r"(b0), "r"(b1))

// ---------------- init: bias sum + zero c + barrier/flag reset ----------------
__global__ void init_kernel(const float* __restrict__ b_ih, const float* __restrict__ b_hh) {
    int i = blockIdx.x * blockDim.x + threadIdx.x;
    if (i < BSZ * HDIM) g_c[i] = 0.0f;
    if (i < G4) g_bias[i] = b_ih[i] + b_hh[i];
    if (i < T_DEC) g_xp_done[i] = 0;
    if (i == 0) { g_bar_cnt = 0; g_bar_gen = 0; }
}

// ---------------- vn = norm_scalar * v / ||v|| ----------------
__global__ void vn_kernel(const float* __restrict__ v, const float* __restrict__ ns) {
    __shared__ float red[256];
    float s = 0.0f;
    for (int i = threadIdx.x; i < HDIM; i += 256) { float x = v[i]; s += x * x; }
    red[threadIdx.x] = s;
    __syncthreads();
    for (int off = 128; off > 0; off >>= 1) {
        if (threadIdx.x < off) red[threadIdx.x] += red[threadIdx.x + off];
        __syncthreads();
    }
    float inv = ns[0] * rsqrtf(red[0]);
    for (int i = threadIdx.x; i < HDIM; i += 256) g_vn[i] = v[i] * inv;
}

// ---------------- embedding gather + 2-chunk split ----------------
__global__ void embed_split(const int* __restrict__ tokens, const float* __restrict__ table) {
    int tb = blockIdx.x;
    int tok = tokens[tb];
    size_t base = (size_t)tb * K2;
#pragma unroll
    for (int j = 0; j < 4; j++) {
        int k = threadIdx.x + j * 256;
        float x = table[(size_t)tok * EDIM + k];
        __nv_bfloat16 h, l; split2(x, h, l);
        g_embs[base + k] = h;
        g_embs[base + EDIM + k] = l;
    }
}

// ---------------- fp32 -> [hi|lo] split ----------------
__global__ void split2_kernel(const float* __restrict__ X, __nv_bfloat16* __restrict__ Y,
                              int K, int total) {
    int idx = blockIdx.x * 256 + threadIdx.x;
    if (idx >= total) return;
    int m = idx / K, k = idx - m * K;
    float x = X[idx];
    __nv_bfloat16 h, l; split2(x, h, l);
    size_t base = (size_t)m * 2 * K;
    Y[base + k] = h;
    Y[base + K + k] = l;
}

// ============================================================================
// Triple-pass split GEMM, 2-stage ring, 2 CTAs/SM (R8/R10-proven config).
// Optional per-M-tile completion flags (done[blockIdx.y] += 1 after epilogue).
// ============================================================================
template<int BM, int BN, int WM, int WN, int NT>
__global__ __launch_bounds__(NT, 2) void gemm3(
    const __nv_bfloat16* __restrict__ A, const __nv_bfloat16* __restrict__ B,
    float* __restrict__ C, int M, int N, int K, unsigned* done)
{
    constexpr int NWN = BN / WN;
    constexpr int MI  = WM / 16;
    constexpr int NJ  = WN / 8;
    constexpr int NLD = WN / 16;
    constexpr int ANUM = BM * 16 / NT;
    constexpr int BNUM = BN * 16 / NT;
    constexpr int SS = 2 * BM * 128 + 2 * BN * 128;

    extern __shared__ __align__(16) unsigned char smem_raw[];
    uint32_t asB = (uint32_t)__cvta_generic_to_shared(smem_raw);

    const int tid  = threadIdx.x;
    const int lane = tid & 31;
    const int w    = tid >> 5;
    const int wm   = w / NWN, wn = w % NWN;
    const int mBase = blockIdx.y * BM;
    const int nBase = blockIdx.x * BN;
    const int Kr = 2 * K;

    float acc[MI][NJ][4];
#pragma unroll
    for (int i = 0; i < MI; i++)
#pragma unroll
        for (int j = 0; j < NJ; j++)
#pragma unroll
            for (int r = 0; r < 4; r++) acc[i][j][r] = 0.0f;

    const int s = lane & 7;
    const int rowA0 = wm * WM + (lane & 7) + ((lane >> 3) & 1) * 8;
    const int cA    = (lane >> 4);
    const int rowB0 = wn * WN + (lane & 7) + ((lane & 16) ? 8 : 0);
    const int cB    = (lane >> 3) & 1;

    const int kIters = K / 64;

    auto issue = [&](int kc, int st) {
        uint32_t sbase = asB + st * SS;
#pragma unroll
        for (int i = 0; i < ANUM; i++) {
            int idx = tid + i * NT;
            int half = idx >= BM * 8 ? 1 : 0;
            int rem = idx - half * BM * 8;
            int r = rem >> 3, c = rem & 7;
            cp16(sbase + half * (BM * 128) + r * 128 + ((c ^ (r & 7)) << 4),
                 A + (size_t)(mBase + r) * Kr + half * K + kc * 64 + c * 8);
        }
        uint32_t bbase = sbase + 2 * BM * 128;
#pragma unroll
        for (int i = 0; i < BNUM; i++) {
            int idx = tid + i * NT;
            int half = idx >= BN * 8 ? 1 : 0;
            int rem = idx - half * BN * 8;
            int r = rem >> 3, c = rem & 7;
            cp16(bbase + half * (BN * 128) + r * 128 + ((c ^ (r & 7)) << 4),
                 B + (size_t)(nBase + r) * Kr + half * K + kc * 64 + c * 8);
        }
        cp_commit();
    };

    issue(0, 0);
    issue(1, 1);

    for (int kc = 0; kc < kIters; kc++) {
        int st = kc & 1;
        if (kc + 1 < kIters) cp_wait1(); else cp_wait0();
        __syncthreads();

        uint32_t aH = asB + st * SS;
        uint32_t aL = aH + BM * 128;
        uint32_t bH = aH + 2 * BM * 128;
        uint32_t bL = bH + BN * 128;

#pragma unroll
        for (int kk = 0; kk < 4; kk++) {
            uint32_t ofA = (((kk * 2 + cA) ^ s) << 4);
            uint32_t ofB = (((kk * 2 + cB) ^ s) << 4);
            uint32_t ahf[MI][4], alf[MI][4];
#pragma unroll
            for (int i = 0; i < MI; i++) {
                int row = rowA0 + i * 16;
                LDMX4(ahf[i][0], ahf[i][1], ahf[i][2], ahf[i][3], aH + row * 128 + ofA);
                LDMX4(alf[i][0], alf[i][1], alf[i][2], alf[i][3], aL + row * 128 + ofA);
            }
            uint32_t bhf[NLD][4], blf[NLD][4];
#pragma unroll
            for (int j = 0; j < NLD; j++) {
                int row = rowB0 + j * 16;
                LDMX4(bhf[j][0], bhf[j][1], bhf[j][2], bhf[j][3], bH + row * 128 + ofB);
                LDMX4(blf[j][0], blf[j][1], blf[j][2], blf[j][3], bL + row * 128 + ofB);
            }
#pragma unroll
            for (int i = 0; i < MI; i++)
#pragma unroll
                for (int j = 0; j < NJ; j++)
                    MMA16816(acc[i][j], ahf[i], bhf[j >> 1][(j & 1) * 2], bhf[j >> 1][(j & 1) * 2 + 1]);
#pragma unroll
            for (int i = 0; i < MI; i++)
#pragma unroll
                for (int j = 0; j < NJ; j++)
                    MMA16816(acc[i][j], alf[i], bhf[j >> 1][(j & 1) * 2], bhf[j >> 1][(j & 1) * 2 + 1]);
#pragma unroll
            for (int i = 0; i < MI; i++)
#pragma unroll
                for (int j = 0; j < NJ; j++)
                    MMA16816(acc[i][j], ahf[i], blf[j >> 1][(j & 1) * 2], blf[j >> 1][(j & 1) * 2 + 1]);
        }

        if (kc + 2 < kIters) {
            __syncthreads();            // all warps done reading slot st
            issue(kc + 2, st);
        }
    }

#pragma unroll
    for (int i = 0; i < MI; i++) {
        int row = mBase + wm * WM + i * 16 + (lane >> 2);
#pragma unroll
        for (int j = 0; j < NJ; j++) {
            int col = nBase + wn * WN + j * 8 + (lane & 3) * 2;
            *(float2*)(C + (size_t)row * N + col)       = make_float2(acc[i][j][0], acc[i][j][1]);
            *(float2*)(C + (size_t)(row + 8) * N + col) = make_float2(acc[i][j][2], acc[i][j][3]);
        }
    }

    if (done) {
        __threadfence();
        __syncthreads();
        if (tid == 0) atomicAdd(&done[blockIdx.y], 1u);
    }
}

// ---------------- persistent LSTM (R10 config) + per-step xp-flag pacing -----
__global__ __launch_bounds__(256) void lstm_persistent(
    const __nv_bfloat16* __restrict__ Whhs, float* __restrict__ rnn_out)
{
    constexpr int BM = 64, BN = 64, WM = 32, WN = 16, NT = 256;
    constexpr int NWN = BN / WN;      // 4
    constexpr int MI = WM / 16;       // 2
    constexpr int NJ = WN / 8;        // 2
    constexpr int ANUM = BM * 16 / NT;// 4
    constexpr int BNUM = BN * 16 / NT;// 4
    constexpr int SS = 2 * BM * 128 + 2 * BN * 128;   // 32KB
    constexpr int NBLOCKS = 128;
    constexpr int K = 1024;
    constexpr unsigned XP_BLOCKS_PER_T = 64;   // xp grid.x = 4096/64

    extern __shared__ __align__(16) unsigned char smem_raw[];
    uint32_t asB = (uint32_t)__cvta_generic_to_shared(smem_raw);
    float* gsh = (float*)smem_raw;

    const int tid  = threadIdx.x;
    const int lane = tid & 31;
    const int w    = tid >> 5;
    const int wm   = w / NWN, wn = w % NWN;
    const int u0   = blockIdx.x * 16;
    const int b0   = blockIdx.y * 64;

    const int s = lane & 7;
    const int rowA0 = wm * WM + (lane & 7) + ((lane >> 3) & 1) * 8;
    const int cA    = (lane >> 4);
    const int rowB0 = wn * WN + (lane & 7) + ((lane & 16) ? 8 : 0);
    const int cB    = (lane >> 3) & 1;

    int aHalf[ANUM], aR[ANUM], aC[ANUM];
    int bHalf[BNUM], bGrow[BNUM], bR[BNUM], bC[BNUM];
#pragma unroll
    for (int i = 0; i < ANUM; i++) {
        int idx = tid + i * NT;
        aHalf[i] = idx >= BM * 8 ? 1 : 0;
        int rem = idx - aHalf[i] * BM * 8;
        aR[i] = rem >> 3; aC[i] = rem & 7;
    }
#pragma unroll
    for (int i = 0; i < BNUM; i++) {
        int idx = tid + i * NT;
        bHalf[i] = idx >= BN * 8 ? 1 : 0;
        int rem = idx - bHalf[i] * BN * 8;
        bR[i] = rem >> 3; bC[i] = rem & 7;
        bGrow[i] = (bR[i] >> 4) * HDIM + u0 + (bR[i] & 15);   // gate*H + u
    }

    unsigned bgen = 0;

    for (int t = 0; t < T_DEC; t++) {
        float acc[MI][NJ][4];
#pragma unroll
        for (int i = 0; i < MI; i++)
#pragma unroll
            for (int j = 0; j < NJ; j++)
#pragma unroll
                for (int r = 0; r < 4; r++) acc[i][j][r] = 0.0f;

        if (t > 0) {
            const __nv_bfloat16* hprev = g_rnns + (size_t)(t - 1) * BSZ * K2;
            auto issue = [&](int kc, int st) {
                uint32_t sbase = asB + st * SS;
#pragma unroll
                for (int i = 0; i < ANUM; i++)
                    cp16(sbase + aHalf[i] * (BM * 128) + aR[i] * 128 + ((aC[i] ^ (aR[i] & 7)) << 4),
                         hprev + (size_t)(b0 + aR[i]) * K2 + aHalf[i] * K + kc * 64 + aC[i] * 8);
                uint32_t bbase = sbase + 2 * BM * 128;
#pragma unroll
                for (int i = 0; i < BNUM; i++)
                    cp16(bbase + bHalf[i] * (BN * 128) + bR[i] * 128 + ((bC[i] ^ (bR[i] & 7)) << 4),
                         Whhs + (size_t)bGrow[i] * K2 + bHalf[i] * K + kc * 64 + bC[i] * 8);
                cp_commit();
            };

            issue(0, 0);
            issue(1, 1);

            const int kIters = K / 64;   // 16
            for (int kc = 0; kc < kIters; kc++) {
                int st = kc % 3;
                if (kc + 1 < kIters) cp_wait1(); else cp_wait0();
                __syncthreads();
                if (kc + 2 < kIters) issue(kc + 2, (kc + 2) % 3);

                uint32_t aH = asB + st * SS;
                uint32_t aL = aH + BM * 128;
                uint32_t bH = aH + 2 * BM * 128;
                uint32_t bL = bH + BN * 128;

#pragma unroll
                for (int kk = 0; kk < 4; kk++) {
                    uint32_t ofA = (((kk * 2 + cA) ^ s) << 4);
                    uint32_t ofB = (((kk * 2 + cB) ^ s) << 4);
                    uint32_t ahf[MI][4], alf[MI][4];
#pragma unroll
                    for (int i = 0; i < MI; i++) {
                        int row = rowA0 + i * 16;
                        LDMX4(ahf[i][0], ahf[i][1], ahf[i][2], ahf[i][3], aH + row * 128 + ofA);
                        LDMX4(alf[i][0], alf[i][1], alf[i][2], alf[i][3], aL + row * 128 + ofA);
                    }
                    uint32_t bhf[4], blf[4];
                    LDMX4(bhf[0], bhf[1], bhf[2], bhf[3], bH + rowB0 * 128 + ofB);
                    LDMX4(blf[0], blf[1], blf[2], blf[3], bL + rowB0 * 128 + ofB);
#pragma unroll
                    for (int i = 0; i < MI; i++)
#pragma unroll
                        for (int j = 0; j < NJ; j++)
                            MMA16816(acc[i][j], ahf[i], bhf[j * 2], bhf[j * 2 + 1]);
#pragma unroll
                    for (int i = 0; i < MI; i++)
#pragma unroll
                        for (int j = 0; j < NJ; j++)
                            MMA16816(acc[i][j], alf[i], bhf[j * 2], bhf[j * 2 + 1]);
#pragma unroll
                    for (int i = 0; i < MI; i++)
#pragma unroll
                        for (int j = 0; j < NJ; j++)
                            MMA16816(acc[i][j], ahf[i], blf[j * 2], blf[j * 2 + 1]);
                }
            }
            __syncthreads();   // all warps done reading stages before gsh aliases them
        } else {
            __syncthreads();
        }

        // stage gates in smem (aliases mainloop buffers)
#pragma unroll
        for (int i = 0; i < MI; i++) {
            int m = wm * WM + i * 16 + (lane >> 2);
#pragma unroll
            for (int j = 0; j < NJ; j++) {
                int col = wn * WN + j * 8 + (lane & 3) * 2;
                gsh[m * 65 + col]           = acc[i][j][0];
                gsh[m * 65 + col + 1]       = acc[i][j][1];
                gsh[(m + 8) * 65 + col]     = acc[i][j][2];
                gsh[(m + 8) * 65 + col + 1] = acc[i][j][3];
            }
        }
        __syncthreads();

        // wait for xp[t] (xp GEMM runs concurrently on another stream)
        if (tid == 0) {
            unsigned v;
            do {
                asm volatile("ld.acquire.gpu.u32 %0, [%1];"
                             : "=r"(v) : "l"(&g_xp_done[t]) : "memory");
                if (v < XP_BLOCKS_PER_T) __nanosleep(128);
            } while (v < XP_BLOCKS_PER_T);
        }
        __syncthreads();

        // fused cell update for the 64b x 16u tile
#pragma unroll
        for (int sIt = 0; sIt < 4; sIt++) {
            int idx = tid + sIt * 256;
            int bl = idx >> 4, uu = idx & 15;
            int b = b0 + bl, u = u0 + uu;
            size_t xb = ((size_t)t * BSZ + b) * G4 + u;
            float gi = gsh[bl * 65 + uu]      + g_bias[u]            + g_xp[xb];
            float gf = gsh[bl * 65 + 16 + uu] + g_bias[u + HDIM]     + g_xp[xb + HDIM];
            float gg = gsh[bl * 65 + 32 + uu] + g_bias[u + 2 * HDIM] + g_xp[xb + 2 * HDIM];
            float go = gsh[bl * 65 + 48 + uu] + g_bias[u + 3 * HDIM] + g_xp[xb + 3 * HDIM];
            float cp = g_c[(size_t)b * HDIM + u];
            float c  = sigm(gf) * cp + sigm(gi) * tanhf(gg);
            float h  = sigm(go) * tanhf(c);
            g_c[(size_t)b * HDIM + u] = c;
            rnn_out[((size_t)t * BSZ + b) * HDIM + u] = h;
            __nv_bfloat16 hh, hl; split2(h, hh, hl);
            size_t rb2 = ((size_t)t * BSZ + b) * K2;
            g_rnns[rb2 + u] = hh;
            g_rnns[rb2 + HDIM + u] = hl;
        }

        // device-wide barrier (skip after final step)
        if (t + 1 < T_DEC) {
            __syncthreads();
            if (tid == 0) {
                __threadfence();
                unsigned target = bgen + 1;
                if (atomicAdd(&g_bar_cnt, 1) == NBLOCKS - 1) {
                    g_bar_cnt = 0;
                    asm volatile("st.release.gpu.u32 [%0], %1;"
                                 :: "l"(&g_bar_gen), "r"(target) : "memory");
                } else {
                    unsigned v;
                    do {
                        __nanosleep(64);
                        asm volatile("ld.acquire.gpu.u32 %0, [%1];"
                                     : "=r"(v) : "l"(&g_bar_gen) : "memory");
                    } while (v < target);
                }
                bgen = target;
            }
            __syncthreads();
        }
    }
}

// ---------------- attention scores + masked softmax (8 tq per block) --------
__global__ __launch_bounds__(256) void scores_kernel(const int* __restrict__ ctx_len,
                                                     const float* __restrict__ att_bias) {
    int tq0 = blockIdx.x * 8, b = blockIdx.y;
    __shared__ float qsh[8][HDIM];
    __shared__ float vnsh[HDIM];
    __shared__ float ssh[8][T_CTX];

    for (int i = threadIdx.x; i < 8 * HDIM; i += 256) {
        int tqi = i >> 10, u = i & 1023;
        qsh[tqi][u] = g_q[((size_t)(tq0 + tqi) * BSZ + b) * HDIM + u] + att_bias[u];
    }
    for (int i = threadIdx.x; i < HDIM; i += 256) vnsh[i] = g_vn[i];
    __syncthreads();

    int w = threadIdx.x >> 5, lane = threadIdx.x & 31;
#pragma unroll
    for (int tkk = 0; tkk < 4; tkk++) {
        int tk = tkk * 8 + w;
        const float* krow = g_k + ((size_t)tk * BSZ + b) * HDIM;
        float sacc[8];
#pragma unroll
        for (int qq = 0; qq < 8; qq++) sacc[qq] = 0.0f;
        for (int u = lane; u < HDIM; u += 32) {
            float kv = krow[u], vn = vnsh[u];
#pragma unroll
            for (int qq = 0; qq < 8; qq++)
                sacc[qq] += tanh_fast(qsh[qq][u] + kv) * vn;
        }
#pragma unroll
        for (int qq = 0; qq < 8; qq++) {
#pragma unroll
            for (int off = 16; off > 0; off >>= 1)
                sacc[qq] += __shfl_xor_sync(0xffffffffu, sacc[qq], off);
            if (lane == 0) ssh[qq][tk] = sacc[qq];
        }
    }
    __syncthreads();

    {
        int tqi = threadIdx.x >> 5;   // 8 warps x 32 lanes = all 256 threads
        float s = ssh[tqi][lane];
        if (lane >= ctx_len[b]) s = -65504.0f;
        float m = s;
#pragma unroll
        for (int off = 16; off > 0; off >>= 1)
            m = fmaxf(m, __shfl_xor_sync(0xffffffffu, m, off));
        float e = __expf(s - m);
        float sum = e;
#pragma unroll
        for (int off = 16; off > 0; off >>= 1)
            sum += __shfl_xor_sync(0xffffffffu, sum, off);
        g_attn[((size_t)b * T_DEC + tq0 + tqi) * T_CTX + lane] = e / sum;
    }
}

// ---------------- attn_out: 16 tq per block, context read once --------------
__global__ __launch_bounds__(256) void attnctx_kernel(
    const float* __restrict__ context, float* __restrict__ attn_out)
{
    int tqh = blockIdx.x * 16, b = blockIdx.y;
    __shared__ float wsh[16][32];
#pragma unroll
    for (int it = 0; it < 2; it++) {
        int i = threadIdx.x + it * 256;
        if (i < 512) {
            int tq = i >> 5, tk = i & 31;
            wsh[tq][tk] = g_attn[((size_t)b * T_DEC + tqh + tq) * T_CTX + tk];
        }
    }
    __syncthreads();

    int c4 = threadIdx.x;
    float acc[16][4];
#pragma unroll
    for (int tq = 0; tq < 16; tq++)
#pragma unroll
        for (int r = 0; r < 4; r++) acc[tq][r] = 0.0f;

#pragma unroll 4
    for (int tk = 0; tk < T_CTX; tk++) {
        float4 v = *(const float4*)(context + ((size_t)tk * BSZ + b) * CDIM + c4 * 4);
#pragma unroll
        for (int tq = 0; tq < 16; tq++) {
            float wt = wsh[tq][tk];
            acc[tq][0] = fmaf(wt, v.x, acc[tq][0]);
            acc[tq][1] = fmaf(wt, v.y, acc[tq][1]);
            acc[tq][2] = fmaf(wt, v.z, acc[tq][2]);
            acc[tq][3] = fmaf(wt, v.w, acc[tq][3]);
        }
    }
#pragma unroll
    for (int tq = 0; tq < 16; tq++)
        *(float4*)(attn_out + ((size_t)(tqh + tq) * BSZ + b) * CDIM + c4 * 4) =
            make_float4(acc[tq][0], acc[tq][1], acc[tq][2], acc[tq][3]);
}

// ---------------- launcher ----------------
extern "C" void kernel_launch(void* const* d_in, const int* in_sizes, int n_in,
                              void* d_out, int out_size)
{
    const int*   ctx_len     = (const int*)  d_in[0];
    const int*   tokens      = (const int*)  d_in[1];
    const float* context     = (const float*)d_in[2];
    const float* emb_table   = (const float*)d_in[3];
    const float* W_ih        = (const float*)d_in[4];
    const float* W_hh        = (const float*)d_in[5];
    const float* b_ih        = (const float*)d_in[6];
    const float* b_hh        = (const float*)d_in[7];
    const float* Wq          = (const float*)d_in[8];
    const float* Wk          = (const float*)d_in[9];
    const float* v_att       = (const float*)d_in[10];
    const float* att_bias    = (const float*)d_in[11];
    const float* norm_scalar = (const float*)d_in[12];

    float* attn_out = (float*)d_out;
    float* rnn_out  = attn_out + (size_t)T_DEC * BSZ * CDIM;

    __nv_bfloat16 *p_embs, *p_Wihs, *p_Whhs, *p_Wqs, *p_Wks, *p_ctxs, *p_rnns;
    float *p_xp, *p_q, *p_k;
    unsigned* p_xpdone;
    cudaGetSymbolAddress((void**)&p_embs, g_embs);
    cudaGetSymbolAddress((void**)&p_Wihs, g_Wihs);
    cudaGetSymbolAddress((void**)&p_Whhs, g_Whhs);
    cudaGetSymbolAddress((void**)&p_Wqs,  g_Wqs);
    cudaGetSymbolAddress((void**)&p_Wks,  g_Wks);
    cudaGetSymbolAddress((void**)&p_ctxs, g_ctxs);
    cudaGetSymbolAddress((void**)&p_rnns, g_rnns);
    cudaGetSymbolAddress((void**)&p_xp,   g_xp);
    cudaGetSymbolAddress((void**)&p_q,    g_q);
    cudaGetSymbolAddress((void**)&p_k,    g_k);
    cudaGetSymbolAddress((void**)&p_xpdone, g_xp_done);

    static cudaStream_t s2 = nullptr, s3 = nullptr;
    static cudaEvent_t evFork = nullptr, evJoin = nullptr, evWhh = nullptr,
                       evInit = nullptr, evLstm = nullptr;
    if (!s2) {
        cudaStreamCreateWithFlags(&s2, cudaStreamNonBlocking);
        cudaStreamCreateWithFlags(&s3, cudaStreamNonBlocking);
        cudaEventCreateWithFlags(&evFork, cudaEventDisableTiming);
        cudaEventCreateWithFlags(&evJoin, cudaEventDisableTiming);
        cudaEventCreateWithFlags(&evWhh,  cudaEventDisableTiming);
        cudaEventCreateWithFlags(&evInit, cudaEventDisableTiming);
        cudaEventCreateWithFlags(&evLstm, cudaEventDisableTiming);
    }

    const int GEMM_SMEM = 2 * (2 * 128 * 128 + 2 * 64 * 128);   // 96KB -> 2 CTAs/SM
    cudaFuncSetAttribute(gemm3<128, 64, 32, 32, 256>,
                         cudaFuncAttributeMaxDynamicSharedMemorySize, GEMM_SMEM);
    const int LSTM_SMEM = 3 * (2 * 64 * 128 + 2 * 64 * 128);    // 96KB
    cudaFuncSetAttribute(lstm_persistent,
                         cudaFuncAttributeMaxDynamicSharedMemorySize, LSTM_SMEM);

    // fork side stream s2 into capture
    cudaEventRecord(evFork, 0);
    cudaStreamWaitEvent(s2, evFork, 0);

    // ---- s2: W_hh split (LSTM dep, off xp's critical path) + k-projection path ----
    split2_kernel<<<(G4 * HDIM + 255) / 256, 256, 0, s2>>>(W_hh, p_Whhs, HDIM, G4 * HDIM);
    cudaEventRecord(evWhh, s2);
    split2_kernel<<<(HDIM * HDIM + 255) / 256, 256, 0, s2>>>(Wq, p_Wqs, HDIM, HDIM * HDIM);
    split2_kernel<<<(HDIM * CDIM + 255) / 256, 256, 0, s2>>>(Wk, p_Wks, CDIM, HDIM * CDIM);
    split2_kernel<<<(T_CTX * BSZ * CDIM + 255) / 256, 256, 0, s2>>>(
        context, p_ctxs, CDIM, T_CTX * BSZ * CDIM);
    gemm3<128, 64, 32, 32, 256>
        <<<dim3(HDIM / 64, (T_CTX * BSZ) / 128), 256, GEMM_SMEM, s2>>>(
        p_ctxs, p_Wks, p_k, T_CTX * BSZ, HDIM, CDIM, nullptr);
    cudaEventRecord(evJoin, s2);

    // ---- main stream: prep (only xp deps + init) ----
    init_kernel<<<(BSZ * HDIM + 255) / 256, 256>>>(b_ih, b_hh);
    cudaEventRecord(evInit, 0);
    vn_kernel<<<1, 256>>>(v_att, norm_scalar);
    embed_split<<<T_DEC * BSZ, 256>>>(tokens, emb_table);
    split2_kernel<<<(G4 * EDIM + 255) / 256, 256>>>(W_ih, p_Wihs, EDIM, G4 * EDIM);

    // ---- s3: persistent LSTM, self-paced on xp flags, CONCURRENT with xp ----
    cudaStreamWaitEvent(s3, evInit, 0);
    cudaStreamWaitEvent(s3, evWhh, 0);
    lstm_persistent<<<dim3(HDIM / 16, BSZ / 64), 256, LSTM_SMEM, s3>>>(p_Whhs, rnn_out);
    cudaEventRecord(evLstm, s3);

    // ---- main stream: xp GEMM with per-t completion flags ----
    gemm3<128, 64, 32, 32, 256>
        <<<dim3(G4 / 64, (T_DEC * BSZ) / 128), 256, GEMM_SMEM>>>(
        p_embs, p_Wihs, p_xp, T_DEC * BSZ, G4, EDIM, p_xpdone);

    // join LSTM + k-path, then q-projection + attention
    cudaStreamWaitEvent(0, evLstm, 0);
    cudaStreamWaitEvent(0, evJoin, 0);

    gemm3<128, 64, 32, 32, 256>
        <<<dim3(HDIM / 64, (T_DEC * BSZ) / 128), 256, GEMM_SMEM>>>(
        p_rnns, p_Wqs, p_q, T_DEC * BSZ, HDIM, HDIM, nullptr);

    scores_kernel<<<dim3(T_DEC / 8, BSZ), 256>>>(ctx_len, att_bias);
    attnctx_kernel<<<dim3(2, BSZ), 256>>>(context, attn_out);
}

// round 13
// speedup vs baseline: 1.3715x; 1.0747x over previous
#include <cuda_runtime.h>
#include <cuda_bf16.h>
#include <cstdint>
#include <cstddef>

#define T_DEC 32
#define T_CTX 32
#define BSZ   128
#define EDIM  1024
#define HDIM  1024
#define CDIM  1024
#define G4    4096   // 4*H
#define K2    2048   // [hi|lo] split storage

// ---------------- scratch (static device globals) ----------------
__device__ __nv_bfloat16 g_embs[T_DEC * BSZ * K2];
__device__ __nv_bfloat16 g_Wihs[G4 * K2];
__device__ __nv_bfloat16 g_Whhs[G4 * K2];
__device__ __nv_bfloat16 g_Wqs [HDIM * K2];
__device__ __nv_bfloat16 g_Wks [HDIM * K2];
__device__ __nv_bfloat16 g_ctxs[T_CTX * BSZ * K2];
__device__ __nv_bfloat16 g_rnns[T_DEC * BSZ * K2];
__device__ float g_xp   [T_DEC * BSZ * G4];
__device__ float g_q    [T_DEC * BSZ * HDIM];
__device__ float g_k    [T_CTX * BSZ * HDIM];
__device__ float g_c    [BSZ * HDIM];
__device__ float g_attn [BSZ * T_DEC * T_CTX];
__device__ float g_bias [G4];
__device__ float g_vn   [HDIM];
__device__ unsigned g_bar_cnt;
__device__ unsigned g_bar_gen;
__device__ unsigned g_xp_done[T_DEC];   // per-timestep xp completion counters

// ---------------- helpers ----------------
__device__ __forceinline__ float tanh_fast(float x) {
    float r; asm("tanh.approx.f32 %0, %1;" : "=f"(r) : "f"(x)); return r;
}
__device__ __forceinline__ float sigm(float x) { return 1.0f / (1.0f + __expf(-x)); }

__device__ __forceinline__ void split2(float x, __nv_bfloat16& h, __nv_bfloat16& l) {
    h = __float2bfloat16_rn(x);
    l = __float2bfloat16_rn(x - __bfloat162float(h));
}

__device__ __forceinline__ void cp16(uint32_t dst, const void* src) {
    asm volatile("cp.async.cg.shared.global [%0], [%1], 16;" :: "r"(dst), "l"(src) : "memory");
}
__device__ __forceinline__ void cp_commit() {
    asm volatile("cp.async.commit_group;" ::: "memory");
}
__device__ __forceinline__ void cp_wait0() {
    asm volatile("cp.async.wait_group 0;" ::: "memory");
}
__device__ __forceinline__ void cp_wait1() {
    asm volatile("cp.async.wait_group 1;" ::: "memory");
}

#define LDMX4(d0,d1,d2,d3,addr) \
    asm volatile("ldmatrix.sync.aligned.m8n8.x4.shared.b16 {%0,%1,%2,%3}, [%4];" \
                 : "=r"(d0), "=r"(d1), "=r"(d2), "=r"(d3) : "r"(addr))

#define MMA16816(acc, a, b0, b1) \
    asm volatile("mma.sync.aligned.m16n8k16.row.col.f32.bf16.bf16.f32 " \
                 "{%0,%1,%2,%3}, {%4,%5,%6,%7}, {%8,%9}, {%0,%1,%2,%3};" \
                 : "+f"((acc)[0]), "+f"((acc)[1]), "+f"((acc)[2]), "+f"((acc)[3]) \
                 : "r"((a)[0]), "r"((a)[1]), "r"((a)[2]), "r"((a)[3]), "r"(b0), "r"(b1))

// ---------------- init: bias sum + zero c + barrier/flag reset ----------------
__global__ void init_kernel(const float* __restrict__ b_ih, const float* __restrict__ b_hh) {
    int i = blockIdx.x * blockDim.x + threadIdx.x;
    if (i < BSZ * HDIM) g_c[i] = 0.0f;
    if (i < G4) g_bias[i] = b_ih[i] + b_hh[i];
    if (i < T_DEC) g_xp_done[i] = 0;
    if (i == 0) { g_bar_cnt = 0; g_bar_gen = 0; }
}

// ---------------- vn = norm_scalar * v / ||v|| ----------------
__global__ void vn_kernel(const float* __restrict__ v, const float* __restrict__ ns) {
    __shared__ float red[256];
    float s = 0.0f;
    for (int i = threadIdx.x; i < HDIM; i += 256) { float x = v[i]; s += x * x; }
    red[threadIdx.x] = s;
    __syncthreads();
    for (int off = 128; off > 0; off >>= 1) {
        if (threadIdx.x < off) red[threadIdx.x] += red[threadIdx.x + off];
        __syncthreads();
    }
    float inv = ns[0] * rsqrtf(red[0]);
    for (int i = threadIdx.x; i < HDIM; i += 256) g_vn[i] = v[i] * inv;
}

// ---------------- embedding gather + 2-chunk split ----------------
__global__ void embed_split(const int* __restrict__ tokens, const float* __restrict__ table) {
    int tb = blockIdx.x;
    int tok = tokens[tb];
    size_t base = (size_t)tb * K2;
#pragma unroll
    for (int j = 0; j < 4; j++) {
        int k = threadIdx.x + j * 256;
        float x = table[(size_t)tok * EDIM + k];
        __nv_bfloat16 h, l; split2(x, h, l);
        g_embs[base + k] = h;
        g_embs[base + EDIM + k] = l;
    }
}

// ---------------- fp32 -> [hi|lo] split ----------------
__global__ void split2_kernel(const float* __restrict__ X, __nv_bfloat16* __restrict__ Y,
                              int K, int total) {
    int idx = blockIdx.x * 256 + threadIdx.x;
    if (idx >= total) return;
    int m = idx / K, k = idx - m * K;
    float x = X[idx];
    __nv_bfloat16 h, l; split2(x, h, l);
    size_t base = (size_t)m * 2 * K;
    Y[base + k] = h;
    Y[base + K + k] = l;
}

// ============================================================================
// Triple-pass split GEMM, 2-stage ring, 2 CTAs/SM (proven config).
// Optional per-M-tile completion flags (done[blockIdx.y] += 1 after epilogue).
// ============================================================================
template<int BM, int BN, int WM, int WN, int NT>
__global__ __launch_bounds__(NT, 2) void gemm3(
    const __nv_bfloat16* __restrict__ A, const __nv_bfloat16* __restrict__ B,
    float* __restrict__ C, int M, int N, int K, unsigned* done)
{
    constexpr int NWN = BN / WN;
    constexpr int MI  = WM / 16;
    constexpr int NJ  = WN / 8;
    constexpr int NLD = WN / 16;
    constexpr int ANUM = BM * 16 / NT;
    constexpr int BNUM = BN * 16 / NT;
    constexpr int SS = 2 * BM * 128 + 2 * BN * 128;

    extern __shared__ __align__(16) unsigned char smem_raw[];
    uint32_t asB = (uint32_t)__cvta_generic_to_shared(smem_raw);

    const int tid  = threadIdx.x;
    const int lane = tid & 31;
    const int w    = tid >> 5;
    const int wm   = w / NWN, wn = w % NWN;
    const int mBase = blockIdx.y * BM;
    const int nBase = blockIdx.x * BN;
    const int Kr = 2 * K;

    float acc[MI][NJ][4];
#pragma unroll
    for (int i = 0; i < MI; i++)
#pragma unroll
        for (int j = 0; j < NJ; j++)
#pragma unroll
            for (int r = 0; r < 4; r++) acc[i][j][r] = 0.0f;

    const int s = lane & 7;
    const int rowA0 = wm * WM + (lane & 7) + ((lane >> 3) & 1) * 8;
    const int cA    = (lane >> 4);
    const int rowB0 = wn * WN + (lane & 7) + ((lane & 16) ? 8 : 0);
    const int cB    = (lane >> 3) & 1;

    const int kIters = K / 64;

    auto issue = [&](int kc, int st) {
        uint32_t sbase = asB + st * SS;
#pragma unroll
        for (int i = 0; i < ANUM; i++) {
            int idx = tid + i * NT;
            int half = idx >= BM * 8 ? 1 : 0;
            int rem = idx - half * BM * 8;
            int r = rem >> 3, c = rem & 7;
            cp16(sbase + half * (BM * 128) + r * 128 + ((c ^ (r & 7)) << 4),
                 A + (size_t)(mBase + r) * Kr + half * K + kc * 64 + c * 8);
        }
        uint32_t bbase = sbase + 2 * BM * 128;
#pragma unroll
        for (int i = 0; i < BNUM; i++) {
            int idx = tid + i * NT;
            int half = idx >= BN * 8 ? 1 : 0;
            int rem = idx - half * BN * 8;
            int r = rem >> 3, c = rem & 7;
            cp16(bbase + half * (BN * 128) + r * 128 + ((c ^ (r & 7)) << 4),
                 B + (size_t)(nBase + r) * Kr + half * K + kc * 64 + c * 8);
        }
        cp_commit();
    };

    issue(0, 0);
    issue(1, 1);

    for (int kc = 0; kc < kIters; kc++) {
        int st = kc & 1;
        if (kc + 1 < kIters) cp_wait1(); else cp_wait0();
        __syncthreads();

        uint32_t aH = asB + st * SS;
        uint32_t aL = aH + BM * 128;
        uint32_t bH = aH + 2 * BM * 128;
        uint32_t bL = bH + BN * 128;

#pragma unroll
        for (int kk = 0; kk < 4; kk++) {
            uint32_t ofA = (((kk * 2 + cA) ^ s) << 4);
            uint32_t ofB = (((kk * 2 + cB) ^ s) << 4);
            uint32_t ahf[MI][4], alf[MI][4];
#pragma unroll
            for (int i = 0; i < MI; i++) {
                int row = rowA0 + i * 16;
                LDMX4(ahf[i][0], ahf[i][1], ahf[i][2], ahf[i][3], aH + row * 128 + ofA);
                LDMX4(alf[i][0], alf[i][1], alf[i][2], alf[i][3], aL + row * 128 + ofA);
            }
            uint32_t bhf[NLD][4], blf[NLD][4];
#pragma unroll
            for (int j = 0; j < NLD; j++) {
                int row = rowB0 + j * 16;
                LDMX4(bhf[j][0], bhf[j][1], bhf[j][2], bhf[j][3], bH + row * 128 + ofB);
                LDMX4(blf[j][0], blf[j][1], blf[j][2], blf[j][3], bL + row * 128 + ofB);
            }
#pragma unroll
            for (int i = 0; i < MI; i++)
#pragma unroll
                for (int j = 0; j < NJ; j++)
                    MMA16816(acc[i][j], ahf[i], bhf[j >> 1][(j & 1) * 2], bhf[j >> 1][(j & 1) * 2 + 1]);
#pragma unroll
            for (int i = 0; i < MI; i++)
#pragma unroll
                for (int j = 0; j < NJ; j++)
                    MMA16816(acc[i][j], alf[i], bhf[j >> 1][(j & 1) * 2], bhf[j >> 1][(j & 1) * 2 + 1]);
#pragma unroll
            for (int i = 0; i < MI; i++)
#pragma unroll
                for (int j = 0; j < NJ; j++)
                    MMA16816(acc[i][j], ahf[i], blf[j >> 1][(j & 1) * 2], blf[j >> 1][(j & 1) * 2 + 1]);
        }

        if (kc + 2 < kIters) {
            __syncthreads();            // all warps done reading slot st
            issue(kc + 2, st);
        }
    }

#pragma unroll
    for (int i = 0; i < MI; i++) {
        int row = mBase + wm * WM + i * 16 + (lane >> 2);
#pragma unroll
        for (int j = 0; j < NJ; j++) {
            int col = nBase + wn * WN + j * 8 + (lane & 3) * 2;
            *(float2*)(C + (size_t)row * N + col)       = make_float2(acc[i][j][0], acc[i][j][1]);
            *(float2*)(C + (size_t)(row + 8) * N + col) = make_float2(acc[i][j][2], acc[i][j][3]);
        }
    }

    if (done) {
        __threadfence();
        __syncthreads();
        if (tid == 0) atomicAdd(&done[blockIdx.y], 1u);
    }
}

// ============================================================================
// Single-pass hi-only GEMM (for q/k; precision budget analyzed): C = Ah @ Bh^T.
// A,B stored [hi|lo] with row stride 2K; only hi halves are read.
// ============================================================================
template<int BM, int BN, int WM, int WN, int NT>
__global__ __launch_bounds__(NT, 2) void gemm1(
    const __nv_bfloat16* __restrict__ A, const __nv_bfloat16* __restrict__ B,
    float* __restrict__ C, int M, int N, int K)
{
    constexpr int NWN = BN / WN;
    constexpr int MI  = WM / 16;
    constexpr int NJ  = WN / 8;
    constexpr int NLD = WN / 16;
    constexpr int ANUM = BM * 8 / NT;
    constexpr int BNUM = BN * 8 / NT;
    constexpr int SS = BM * 128 + BN * 128;

    extern __shared__ __align__(16) unsigned char smem_raw[];
    uint32_t asB = (uint32_t)__cvta_generic_to_shared(smem_raw);

    const int tid  = threadIdx.x;
    const int lane = tid & 31;
    const int w    = tid >> 5;
    const int wm   = w / NWN, wn = w % NWN;
    const int mBase = blockIdx.y * BM;
    const int nBase = blockIdx.x * BN;
    const int Kr = 2 * K;

    float acc[MI][NJ][4];
#pragma unroll
    for (int i = 0; i < MI; i++)
#pragma unroll
        for (int j = 0; j < NJ; j++)
#pragma unroll
            for (int r = 0; r < 4; r++) acc[i][j][r] = 0.0f;

    const int s = lane & 7;
    const int rowA0 = wm * WM + (lane & 7) + ((lane >> 3) & 1) * 8;
    const int cA    = (lane >> 4);
    const int rowB0 = wn * WN + (lane & 7) + ((lane & 16) ? 8 : 0);
    const int cB    = (lane >> 3) & 1;

    const int kIters = K / 64;

    auto issue = [&](int kc, int st) {
        uint32_t sbase = asB + st * SS;
#pragma unroll
        for (int i = 0; i < ANUM; i++) {
            int idx = tid + i * NT;
            int r = idx >> 3, c = idx & 7;
            cp16(sbase + r * 128 + ((c ^ (r & 7)) << 4),
                 A + (size_t)(mBase + r) * Kr + kc * 64 + c * 8);
        }
        uint32_t bbase = sbase + BM * 128;
#pragma unroll
        for (int i = 0; i < BNUM; i++) {
            int idx = tid + i * NT;
            int r = idx >> 3, c = idx & 7;
            cp16(bbase + r * 128 + ((c ^ (r & 7)) << 4),
                 B + (size_t)(nBase + r) * Kr + kc * 64 + c * 8);
        }
        cp_commit();
    };

    issue(0, 0);
    issue(1, 1);

    for (int kc = 0; kc < kIters; kc++) {
        int st = kc & 1;
        if (kc + 1 < kIters) cp_wait1(); else cp_wait0();
        __syncthreads();

        uint32_t aH = asB + st * SS;
        uint32_t bH = aH + BM * 128;

#pragma unroll
        for (int kk = 0; kk < 4; kk++) {
            uint32_t ofA = (((kk * 2 + cA) ^ s) << 4);
            uint32_t ofB = (((kk * 2 + cB) ^ s) << 4);
            uint32_t ahf[MI][4];
#pragma unroll
            for (int i = 0; i < MI; i++) {
                int row = rowA0 + i * 16;
                LDMX4(ahf[i][0], ahf[i][1], ahf[i][2], ahf[i][3], aH + row * 128 + ofA);
            }
            uint32_t bhf[NLD][4];
#pragma unroll
            for (int j = 0; j < NLD; j++) {
                int row = rowB0 + j * 16;
                LDMX4(bhf[j][0], bhf[j][1], bhf[j][2], bhf[j][3], bH + row * 128 + ofB);
            }
#pragma unroll
            for (int i = 0; i < MI; i++)
#pragma unroll
                for (int j = 0; j < NJ; j++)
                    MMA16816(acc[i][j], ahf[i], bhf[j >> 1][(j & 1) * 2], bhf[j >> 1][(j & 1) * 2 + 1]);
        }

        if (kc + 2 < kIters) {
            __syncthreads();
            issue(kc + 2, st);
        }
    }

#pragma unroll
    for (int i = 0; i < MI; i++) {
        int row = mBase + wm * WM + i * 16 + (lane >> 2);
#pragma unroll
        for (int j = 0; j < NJ; j++) {
            int col = nBase + wn * WN + j * 8 + (lane & 3) * 2;
            *(float2*)(C + (size_t)row * N + col)       = make_float2(acc[i][j][0], acc[i][j][1]);
            *(float2*)(C + (size_t)(row + 8) * N + col) = make_float2(acc[i][j][2], acc[i][j][3]);
        }
    }
}

// ---------------- persistent LSTM (R10 config) + per-step xp-flag pacing -----
__global__ __launch_bounds__(256) void lstm_persistent(
    const __nv_bfloat16* __restrict__ Whhs, float* __restrict__ rnn_out)
{
    constexpr int BM = 64, BN = 64, WM = 32, WN = 16, NT = 256;
    constexpr int NWN = BN / WN;      // 4
    constexpr int MI = WM / 16;       // 2
    constexpr int NJ = WN / 8;        // 2
    constexpr int ANUM = BM * 16 / NT;// 4
    constexpr int BNUM = BN * 16 / NT;// 4
    constexpr int SS = 2 * BM * 128 + 2 * BN * 128;   // 32KB
    constexpr int NBLOCKS = 128;
    constexpr int K = 1024;
    constexpr unsigned XP_BLOCKS_PER_T = 64;   // xp grid.x = 4096/64

    extern __shared__ __align__(16) unsigned char smem_raw[];
    uint32_t asB = (uint32_t)__cvta_generic_to_shared(smem_raw);
    float* gsh = (float*)smem_raw;

    const int tid  = threadIdx.x;
    const int lane = tid & 31;
    const int w    = tid >> 5;
    const int wm   = w / NWN, wn = w % NWN;
    const int u0   = blockIdx.x * 16;
    const int b0   = blockIdx.y * 64;

    const int s = lane & 7;
    const int rowA0 = wm * WM + (lane & 7) + ((lane >> 3) & 1) * 8;
    const int cA    = (lane >> 4);
    const int rowB0 = wn * WN + (lane & 7) + ((lane & 16) ? 8 : 0);
    const int cB    = (lane >> 3) & 1;

    int aHalf[ANUM], aR[ANUM], aC[ANUM];
    int bHalf[BNUM], bGrow[BNUM], bR[BNUM], bC[BNUM];
#pragma unroll
    for (int i = 0; i < ANUM; i++) {
        int idx = tid + i * NT;
        aHalf[i] = idx >= BM * 8 ? 1 : 0;
        int rem = idx - aHalf[i] * BM * 8;
        aR[i] = rem >> 3; aC[i] = rem & 7;
    }
#pragma unroll
    for (int i = 0; i < BNUM; i++) {
        int idx = tid + i * NT;
        bHalf[i] = idx >= BN * 8 ? 1 : 0;
        int rem = idx - bHalf[i] * BN * 8;
        bR[i] = rem >> 3; bC[i] = rem & 7;
        bGrow[i] = (bR[i] >> 4) * HDIM + u0 + (bR[i] & 15);   // gate*H + u
    }

    unsigned bgen = 0;

    for (int t = 0; t < T_DEC; t++) {
        float acc[MI][NJ][4];
#pragma unroll
        for (int i = 0; i < MI; i++)
#pragma unroll
            for (int j = 0; j < NJ; j++)
#pragma unroll
                for (int r = 0; r < 4; r++) acc[i][j][r] = 0.0f;

        if (t > 0) {
            const __nv_bfloat16* hprev = g_rnns + (size_t)(t - 1) * BSZ * K2;
            auto issue = [&](int kc, int st) {
                uint32_t sbase = asB + st * SS;
#pragma unroll
                for (int i = 0; i < ANUM; i++)
                    cp16(sbase + aHalf[i] * (BM * 128) + aR[i] * 128 + ((aC[i] ^ (aR[i] & 7)) << 4),
                         hprev + (size_t)(b0 + aR[i]) * K2 + aHalf[i] * K + kc * 64 + aC[i] * 8);
                uint32_t bbase = sbase + 2 * BM * 128;
#pragma unroll
                for (int i = 0; i < BNUM; i++)
                    cp16(bbase + bHalf[i] * (BN * 128) + bR[i] * 128 + ((bC[i] ^ (bR[i] & 7)) << 4),
                         Whhs + (size_t)bGrow[i] * K2 + bHalf[i] * K + kc * 64 + bC[i] * 8);
                cp_commit();
            };

            issue(0, 0);
            issue(1, 1);

            const int kIters = K / 64;   // 16
            for (int kc = 0; kc < kIters; kc++) {
                int st = kc % 3;
                if (kc + 1 < kIters) cp_wait1(); else cp_wait0();
                __syncthreads();
                if (kc + 2 < kIters) issue(kc + 2, (kc + 2) % 3);

                uint32_t aH = asB + st * SS;
                uint32_t aL = aH + BM * 128;
                uint32_t bH = aH + 2 * BM * 128;
                uint32_t bL = bH + BN * 128;

#pragma unroll
                for (int kk = 0; kk < 4; kk++) {
                    uint32_t ofA = (((kk * 2 + cA) ^ s) << 4);
                    uint32_t ofB = (((kk * 2 + cB) ^ s) << 4);
                    uint32_t ahf[MI][4], alf[MI][4];
#pragma unroll
                    for (int i = 0; i < MI; i++) {
                        int row = rowA0 + i * 16;
                        LDMX4(ahf[i][0], ahf[i][1], ahf[i][2], ahf[i][3], aH + row * 128 + ofA);
                        LDMX4(alf[i][0], alf[i][1], alf[i][2], alf[i][3], aL + row * 128 + ofA);
                    }
                    uint32_t bhf[4], blf[4];
                    LDMX4(bhf[0], bhf[1], bhf[2], bhf[3], bH + rowB0 * 128 + ofB);
                    LDMX4(blf[0], blf[1], blf[2], blf[3], bL + rowB0 * 128 + ofB);
#pragma unroll
                    for (int i = 0; i < MI; i++)
#pragma unroll
                        for (int j = 0; j < NJ; j++)
                            MMA16816(acc[i][j], ahf[i], bhf[j * 2], bhf[j * 2 + 1]);
#pragma unroll
                    for (int i = 0; i < MI; i++)
#pragma unroll
                        for (int j = 0; j < NJ; j++)
                            MMA16816(acc[i][j], alf[i], bhf[j * 2], bhf[j * 2 + 1]);
#pragma unroll
                    for (int i = 0; i < MI; i++)
#pragma unroll
                        for (int j = 0; j < NJ; j++)
                            MMA16816(acc[i][j], ahf[i], blf[j * 2], blf[j * 2 + 1]);
                }
            }
            __syncthreads();   // all warps done reading stages before gsh aliases them
        } else {
            __syncthreads();
        }

        // stage gates in smem (aliases mainloop buffers)
#pragma unroll
        for (int i = 0; i < MI; i++) {
            int m = wm * WM + i * 16 + (lane >> 2);
#pragma unroll
            for (int j = 0; j < NJ; j++) {
                int col = wn * WN + j * 8 + (lane & 3) * 2;
                gsh[m * 65 + col]           = acc[i][j][0];
                gsh[m * 65 + col + 1]       = acc[i][j][1];
                gsh[(m + 8) * 65 + col]     = acc[i][j][2];
                gsh[(m + 8) * 65 + col + 1] = acc[i][j][3];
            }
        }
        __syncthreads();

        // wait for xp[t] (xp GEMM runs concurrently on another stream)
        if (tid == 0) {
            unsigned v;
            do {
                asm volatile("ld.acquire.gpu.u32 %0, [%1];"
                             : "=r"(v) : "l"(&g_xp_done[t]) : "memory");
                if (v < XP_BLOCKS_PER_T) __nanosleep(128);
            } while (v < XP_BLOCKS_PER_T);
        }
        __syncthreads();

        // fused cell update for the 64b x 16u tile
#pragma unroll
        for (int sIt = 0; sIt < 4; sIt++) {
            int idx = tid + sIt * 256;
            int bl = idx >> 4, uu = idx & 15;
            int b = b0 + bl, u = u0 + uu;
            size_t xb = ((size_t)t * BSZ + b) * G4 + u;
            float gi = gsh[bl * 65 + uu]      + g_bias[u]            + g_xp[xb];
            float gf = gsh[bl * 65 + 16 + uu] + g_bias[u + HDIM]     + g_xp[xb + HDIM];
            float gg = gsh[bl * 65 + 32 + uu] + g_bias[u + 2 * HDIM] + g_xp[xb + 2 * HDIM];
            float go = gsh[bl * 65 + 48 + uu] + g_bias[u + 3 * HDIM] + g_xp[xb + 3 * HDIM];
            float cp = g_c[(size_t)b * HDIM + u];
            float c  = sigm(gf) * cp + sigm(gi) * tanhf(gg);
            float h  = sigm(go) * tanhf(c);
            g_c[(size_t)b * HDIM + u] = c;
            rnn_out[((size_t)t * BSZ + b) * HDIM + u] = h;
            __nv_bfloat16 hh, hl; split2(h, hh, hl);
            size_t rb2 = ((size_t)t * BSZ + b) * K2;
            g_rnns[rb2 + u] = hh;
            g_rnns[rb2 + HDIM + u] = hl;
        }

        // device-wide barrier (skip after final step)
        if (t + 1 < T_DEC) {
            __syncthreads();
            if (tid == 0) {
                __threadfence();
                unsigned target = bgen + 1;
                if (atomicAdd(&g_bar_cnt, 1) == NBLOCKS - 1) {
                    g_bar_cnt = 0;
                    asm volatile("st.release.gpu.u32 [%0], %1;"
                                 :: "l"(&g_bar_gen), "r"(target) : "memory");
                } else {
                    unsigned v;
                    do {
                        __nanosleep(64);
                        asm volatile("ld.acquire.gpu.u32 %0, [%1];"
                                     : "=r"(v) : "l"(&g_bar_gen) : "memory");
                    } while (v < target);
                }
                bgen = target;
            }
            __syncthreads();
        }
    }
}

// ---------------- attention scores + masked softmax (8 tq per block) --------
__global__ __launch_bounds__(256) void scores_kernel(const int* __restrict__ ctx_len,
                                                     const float* __restrict__ att_bias) {
    int tq0 = blockIdx.x * 8, b = blockIdx.y;
    __shared__ float qsh[8][HDIM];
    __shared__ float vnsh[HDIM];
    __shared__ float ssh[8][T_CTX];

    for (int i = threadIdx.x; i < 8 * HDIM; i += 256) {
        int tqi = i >> 10, u = i & 1023;
        qsh[tqi][u] = g_q[((size_t)(tq0 + tqi) * BSZ + b) * HDIM + u] + att_bias[u];
    }
    for (int i = threadIdx.x; i < HDIM; i += 256) vnsh[i] = g_vn[i];
    __syncthreads();

    int w = threadIdx.x >> 5, lane = threadIdx.x & 31;
#pragma unroll
    for (int tkk = 0; tkk < 4; tkk++) {
        int tk = tkk * 8 + w;
        const float* krow = g_k + ((size_t)tk * BSZ + b) * HDIM;
        float sacc[8];
#pragma unroll
        for (int qq = 0; qq < 8; qq++) sacc[qq] = 0.0f;
        for (int u = lane; u < HDIM; u += 32) {
            float kv = krow[u], vn = vnsh[u];
#pragma unroll
            for (int qq = 0; qq < 8; qq++)
                sacc[qq] += tanh_fast(qsh[qq][u] + kv) * vn;
        }
#pragma unroll
        for (int qq = 0; qq < 8; qq++) {
#pragma unroll
            for (int off = 16; off > 0; off >>= 1)
                sacc[qq] += __shfl_xor_sync(0xffffffffu, sacc[qq], off);
            if (lane == 0) ssh[qq][tk] = sacc[qq];
        }
    }
    __syncthreads();

    {
        int tqi = threadIdx.x >> 5;   // 8 warps x 32 lanes = all 256 threads
        float s = ssh[tqi][lane];
        if (lane >= ctx_len[b]) s = -65504.0f;
        float m = s;
#pragma unroll
        for (int off = 16; off > 0; off >>= 1)
            m = fmaxf(m, __shfl_xor_sync(0xffffffffu, m, off));
        float e = __expf(s - m);
        float sum = e;
#pragma unroll
        for (int off = 16; off > 0; off >>= 1)
            sum += __shfl_xor_sync(0xffffffffu, sum, off);
        g_attn[((size_t)b * T_DEC + tq0 + tqi) * T_CTX + lane] = e / sum;
    }
}

// ---------------- attn_out: 16 tq per block, context read once --------------
__global__ __launch_bounds__(256) void attnctx_kernel(
    const float* __restrict__ context, float* __restrict__ attn_out)
{
    int tqh = blockIdx.x * 16, b = blockIdx.y;
    __shared__ float wsh[16][32];
#pragma unroll
    for (int it = 0; it < 2; it++) {
        int i = threadIdx.x + it * 256;
        if (i < 512) {
            int tq = i >> 5, tk = i & 31;
            wsh[tq][tk] = g_attn[((size_t)b * T_DEC + tqh + tq) * T_CTX + tk];
        }
    }
    __syncthreads();

    int c4 = threadIdx.x;
    float acc[16][4];
#pragma unroll
    for (int tq = 0; tq < 16; tq++)
#pragma unroll
        for (int r = 0; r < 4; r++) acc[tq][r] = 0.0f;

#pragma unroll 4
    for (int tk = 0; tk < T_CTX; tk++) {
        float4 v = *(const float4*)(context + ((size_t)tk * BSZ + b) * CDIM + c4 * 4);
#pragma unroll
        for (int tq = 0; tq < 16; tq++) {
            float wt = wsh[tq][tk];
            acc[tq][0] = fmaf(wt, v.x, acc[tq][0]);
            acc[tq][1] = fmaf(wt, v.y, acc[tq][1]);
            acc[tq][2] = fmaf(wt, v.z, acc[tq][2]);
            acc[tq][3] = fmaf(wt, v.w, acc[tq][3]);
        }
    }
#pragma unroll
    for (int tq = 0; tq < 16; tq++)
        *(float4*)(attn_out + ((size_t)(tqh + tq) * BSZ + b) * CDIM + c4 * 4) =
            make_float4(acc[tq][0], acc[tq][1], acc[tq][2], acc[tq][3]);
}

// ---------------- launcher ----------------
extern "C" void kernel_launch(void* const* d_in, const int* in_sizes, int n_in,
                              void* d_out, int out_size)
{
    const int*   ctx_len     = (const int*)  d_in[0];
    const int*   tokens      = (const int*)  d_in[1];
    const float* context     = (const float*)d_in[2];
    const float* emb_table   = (const float*)d_in[3];
    const float* W_ih        = (const float*)d_in[4];
    const float* W_hh        = (const float*)d_in[5];
    const float* b_ih        = (const float*)d_in[6];
    const float* b_hh        = (const float*)d_in[7];
    const float* Wq          = (const float*)d_in[8];
    const float* Wk          = (const float*)d_in[9];
    const float* v_att       = (const float*)d_in[10];
    const float* att_bias    = (const float*)d_in[11];
    const float* norm_scalar = (const float*)d_in[12];

    float* attn_out = (float*)d_out;
    float* rnn_out  = attn_out + (size_t)T_DEC * BSZ * CDIM;

    __nv_bfloat16 *p_embs, *p_Wihs, *p_Whhs, *p_Wqs, *p_Wks, *p_ctxs, *p_rnns;
    float *p_xp, *p_q, *p_k;
    unsigned* p_xpdone;
    cudaGetSymbolAddress((void**)&p_embs, g_embs);
    cudaGetSymbolAddress((void**)&p_Wihs, g_Wihs);
    cudaGetSymbolAddress((void**)&p_Whhs, g_Whhs);
    cudaGetSymbolAddress((void**)&p_Wqs,  g_Wqs);
    cudaGetSymbolAddress((void**)&p_Wks,  g_Wks);
    cudaGetSymbolAddress((void**)&p_ctxs, g_ctxs);
    cudaGetSymbolAddress((void**)&p_rnns, g_rnns);
    cudaGetSymbolAddress((void**)&p_xp,   g_xp);
    cudaGetSymbolAddress((void**)&p_q,    g_q);
    cudaGetSymbolAddress((void**)&p_k,    g_k);
    cudaGetSymbolAddress((void**)&p_xpdone, g_xp_done);

    static cudaStream_t s2 = nullptr, s3 = nullptr;
    static cudaEvent_t evFork = nullptr, evJoin = nullptr, evWhh = nullptr,
                       evInit = nullptr, evLstm = nullptr;
    if (!s2) {
        cudaStreamCreateWithFlags(&s2, cudaStreamNonBlocking);
        cudaStreamCreateWithFlags(&s3, cudaStreamNonBlocking);
        cudaEventCreateWithFlags(&evFork, cudaEventDisableTiming);
        cudaEventCreateWithFlags(&evJoin, cudaEventDisableTiming);
        cudaEventCreateWithFlags(&evWhh,  cudaEventDisableTiming);
        cudaEventCreateWithFlags(&evInit, cudaEventDisableTiming);
        cudaEventCreateWithFlags(&evLstm, cudaEventDisableTiming);
    }

    const int GEMM_SMEM = 2 * (2 * 128 * 128 + 2 * 64 * 128);   // 96KB -> 2 CTAs/SM
    cudaFuncSetAttribute(gemm3<128, 64, 32, 32, 256>,
                         cudaFuncAttributeMaxDynamicSharedMemorySize, GEMM_SMEM);
    const int GEMM1_SMEM = 2 * (128 * 128 + 64 * 128);          // 48KB -> 2 CTAs/SM
    cudaFuncSetAttribute(gemm1<128, 64, 32, 32, 256>,
                         cudaFuncAttributeMaxDynamicSharedMemorySize, GEMM1_SMEM);
    const int LSTM_SMEM = 3 * (2 * 64 * 128 + 2 * 64 * 128);    // 96KB
    cudaFuncSetAttribute(lstm_persistent,
                         cudaFuncAttributeMaxDynamicSharedMemorySize, LSTM_SMEM);

    // fork side stream s2 into capture
    cudaEventRecord(evFork, 0);
    cudaStreamWaitEvent(s2, evFork, 0);

    // ---- s2: W_hh split (LSTM dep) + k-projection path ----
    split2_kernel<<<(G4 * HDIM + 255) / 256, 256, 0, s2>>>(W_hh, p_Whhs, HDIM, G4 * HDIM);
    cudaEventRecord(evWhh, s2);
    split2_kernel<<<(HDIM * HDIM + 255) / 256, 256, 0, s2>>>(Wq, p_Wqs, HDIM, HDIM * HDIM);
    split2_kernel<<<(HDIM * CDIM + 255) / 256, 256, 0, s2>>>(Wk, p_Wks, CDIM, HDIM * CDIM);
    split2_kernel<<<(T_CTX * BSZ * CDIM + 255) / 256, 256, 0, s2>>>(
        context, p_ctxs, CDIM, T_CTX * BSZ * CDIM);
    gemm1<128, 64, 32, 32, 256>
        <<<dim3(HDIM / 64, (T_CTX * BSZ) / 128), 256, GEMM1_SMEM, s2>>>(
        p_ctxs, p_Wks, p_k, T_CTX * BSZ, HDIM, CDIM);
    cudaEventRecord(evJoin, s2);

    // ---- main stream: prep (only xp deps + init) ----
    init_kernel<<<(BSZ * HDIM + 255) / 256, 256>>>(b_ih, b_hh);
    cudaEventRecord(evInit, 0);
    vn_kernel<<<1, 256>>>(v_att, norm_scalar);
    embed_split<<<T_DEC * BSZ, 256>>>(tokens, emb_table);
    split2_kernel<<<(G4 * EDIM + 255) / 256, 256>>>(W_ih, p_Wihs, EDIM, G4 * EDIM);

    // ---- s3: persistent LSTM, self-paced on xp flags, CONCURRENT with xp ----
    cudaStreamWaitEvent(s3, evInit, 0);
    cudaStreamWaitEvent(s3, evWhh, 0);
    lstm_persistent<<<dim3(HDIM / 16, BSZ / 64), 256, LSTM_SMEM, s3>>>(p_Whhs, rnn_out);
    cudaEventRecord(evLstm, s3);

    // ---- main stream: xp GEMM with per-t completion flags ----
    gemm3<128, 64, 32, 32, 256>
        <<<dim3(G4 / 64, (T_DEC * BSZ) / 128), 256, GEMM_SMEM>>>(
        p_embs, p_Wihs, p_xp, T_DEC * BSZ, G4, EDIM, p_xpdone);

    // join LSTM + k-path, then q-projection (single-pass) + attention
    cudaStreamWaitEvent(0, evLstm, 0);
    cudaStreamWaitEvent(0, evJoin, 0);

    gemm1<128, 64, 32, 32, 256>
        <<<dim3(HDIM / 64, (T_DEC * BSZ) / 128), 256, GEMM1_SMEM>>>(
        p_rnns, p_Wqs, p_q, T_DEC * BSZ, HDIM, HDIM);

    scores_kernel<<<dim3(T_DEC / 8, BSZ), 256>>>(ctx_len, att_bias);
    attnctx_kernel<<<dim3(2, BSZ), 256>>>(context, attn_out);
}

// round 14
// speedup vs baseline: 1.3877x; 1.0119x over previous
#include <cuda_runtime.h>
#include <cuda_bf16.h>
#include <cstdint>
#include <cstddef>

#define T_DEC 32
#define T_CTX 32
#define BSZ   128
#define EDIM  1024
#define HDIM  1024
#define CDIM  1024
#define G4    4096   // 4*H
#define K2    2048   // [hi|lo] split storage

// ---------------- scratch (static device globals) ----------------
__device__ __nv_bfloat16 g_embs[T_DEC * BSZ * K2];
__device__ __nv_bfloat16 g_Wihs[G4 * K2];
__device__ __nv_bfloat16 g_Whhs[G4 * K2];
__device__ __nv_bfloat16 g_Wqs [HDIM * K2];
__device__ __nv_bfloat16 g_Wks [HDIM * K2];
__device__ __nv_bfloat16 g_ctxs[T_CTX * BSZ * K2];
__device__ __nv_bfloat16 g_rnns[T_DEC * BSZ * K2];
__device__ float g_xp   [T_DEC * BSZ * G4];
__device__ float g_q    [T_DEC * BSZ * HDIM];
__device__ float g_k    [T_CTX * BSZ * HDIM];
__device__ float g_c    [BSZ * HDIM];
__device__ float g_attn [BSZ * T_DEC * T_CTX];
__device__ float g_bias [G4];
__device__ float g_vn   [HDIM];
__device__ unsigned g_bar_cnt;
__device__ unsigned g_bar_gen;
__device__ unsigned g_xp_done[T_DEC];   // per-timestep xp completion counters

// ---------------- helpers ----------------
__device__ __forceinline__ float tanh_fast(float x) {
    float r; asm("tanh.approx.f32 %0, %1;" : "=f"(r) : "f"(x)); return r;
}
__device__ __forceinline__ float sigm(float x) { return 1.0f / (1.0f + __expf(-x)); }

__device__ __forceinline__ void split2(float x, __nv_bfloat16& h, __nv_bfloat16& l) {
    h = __float2bfloat16_rn(x);
    l = __float2bfloat16_rn(x - __bfloat162float(h));
}

__device__ __forceinline__ void cp16(uint32_t dst, const void* src) {
    asm volatile("cp.async.cg.shared.global [%0], [%1], 16;" :: "r"(dst), "l"(src) : "memory");
}
__device__ __forceinline__ void cp_commit() {
    asm volatile("cp.async.commit_group;" ::: "memory");
}
__device__ __forceinline__ void cp_wait0() {
    asm volatile("cp.async.wait_group 0;" ::: "memory");
}
__device__ __forceinline__ void cp_wait1() {
    asm volatile("cp.async.wait_group 1;" ::: "memory");
}

#define LDMX4(d0,d1,d2,d3,addr) \
    asm volatile("ldmatrix.sync.aligned.m8n8.x4.shared.b16 {%0,%1,%2,%3}, [%4];" \
                 : "=r"(d0), "=r"(d1), "=r"(d2), "=r"(d3) : "r"(addr))

#define MMA16816(acc, a, b0, b1) \
    asm volatile("mma.sync.aligned.m16n8k16.row.col.f32.bf16.bf16.f32 " \
                 "{%0,%1,%2,%3}, {%4,%5,%6,%7}, {%8,%9}, {%0,%1,%2,%3};" \
                 : "+f"((acc)[0]), "+f"((acc)[1]), "+f"((acc)[2]), "+f"((acc)[3]) \
                 : "r"((a)[0]), "r"((a)[1]), "r"((a)[2]), "r"((a)[3]), "r"(b0), "r"(b1))

// ---------------- init: bias sum + zero c + barrier/flag reset ----------------
__global__ void init_kernel(const float* __restrict__ b_ih, const float* __restrict__ b_hh) {
    int i = blockIdx.x * blockDim.x + threadIdx.x;
    if (i < BSZ * HDIM) g_c[i] = 0.0f;
    if (i < G4) g_bias[i] = b_ih[i] + b_hh[i];
    if (i < T_DEC) g_xp_done[i] = 0;
    if (i == 0) { g_bar_cnt = 0; g_bar_gen = 0; }
}

// ---------------- vn = norm_scalar * v / ||v|| ----------------
__global__ void vn_kernel(const float* __restrict__ v, const float* __restrict__ ns) {
    __shared__ float red[256];
    float s = 0.0f;
    for (int i = threadIdx.x; i < HDIM; i += 256) { float x = v[i]; s += x * x; }
    red[threadIdx.x] = s;
    __syncthreads();
    for (int off = 128; off > 0; off >>= 1) {
        if (threadIdx.x < off) red[threadIdx.x] += red[threadIdx.x + off];
        __syncthreads();
    }
    float inv = ns[0] * rsqrtf(red[0]);
    for (int i = threadIdx.x; i < HDIM; i += 256) g_vn[i] = v[i] * inv;
}

// ---------------- embedding gather + 2-chunk split ----------------
__global__ void embed_split(const int* __restrict__ tokens, const float* __restrict__ table) {
    int tb = blockIdx.x;
    int tok = tokens[tb];
    size_t base = (size_t)tb * K2;
#pragma unroll
    for (int j = 0; j < 4; j++) {
        int k = threadIdx.x + j * 256;
        float x = table[(size_t)tok * EDIM + k];
        __nv_bfloat16 h, l; split2(x, h, l);
        g_embs[base + k] = h;
        g_embs[base + EDIM + k] = l;
    }
}

// ---------------- fp32 -> [hi|lo] split ----------------
__global__ void split2_kernel(const float* __restrict__ X, __nv_bfloat16* __restrict__ Y,
                              int K, int total) {
    int idx = blockIdx.x * 256 + threadIdx.x;
    if (idx >= total) return;
    int m = idx / K, k = idx - m * K;
    float x = X[idx];
    __nv_bfloat16 h, l; split2(x, h, l);
    size_t base = (size_t)m * 2 * K;
    Y[base + k] = h;
    Y[base + K + k] = l;
}

// ============================================================================
// Triple-pass split GEMM, 2-stage ring, 2 CTAs/SM (proven config).
// Optional per-M-tile completion flags (done[blockIdx.y] += 1 after epilogue).
// ============================================================================
template<int BM, int BN, int WM, int WN, int NT>
__global__ __launch_bounds__(NT, 2) void gemm3(
    const __nv_bfloat16* __restrict__ A, const __nv_bfloat16* __restrict__ B,
    float* __restrict__ C, int M, int N, int K, unsigned* done)
{
    constexpr int NWN = BN / WN;
    constexpr int MI  = WM / 16;
    constexpr int NJ  = WN / 8;
    constexpr int NLD = WN / 16;
    constexpr int ANUM = BM * 16 / NT;
    constexpr int BNUM = BN * 16 / NT;
    constexpr int SS = 2 * BM * 128 + 2 * BN * 128;

    extern __shared__ __align__(16) unsigned char smem_raw[];
    uint32_t asB = (uint32_t)__cvta_generic_to_shared(smem_raw);

    const int tid  = threadIdx.x;
    const int lane = tid & 31;
    const int w    = tid >> 5;
    const int wm   = w / NWN, wn = w % NWN;
    const int mBase = blockIdx.y * BM;
    const int nBase = blockIdx.x * BN;
    const int Kr = 2 * K;

    float acc[MI][NJ][4];
#pragma unroll
    for (int i = 0; i < MI; i++)
#pragma unroll
        for (int j = 0; j < NJ; j++)
#pragma unroll
            for (int r = 0; r < 4; r++) acc[i][j][r] = 0.0f;

    const int s = lane & 7;
    const int rowA0 = wm * WM + (lane & 7) + ((lane >> 3) & 1) * 8;
    const int cA    = (lane >> 4);
    const int rowB0 = wn * WN + (lane & 7) + ((lane & 16) ? 8 : 0);
    const int cB    = (lane >> 3) & 1;

    const int kIters = K / 64;

    auto issue = [&](int kc, int st) {
        uint32_t sbase = asB + st * SS;
#pragma unroll
        for (int i = 0; i < ANUM; i++) {
            int idx = tid + i * NT;
            int half = idx >= BM * 8 ? 1 : 0;
            int rem = idx - half * BM * 8;
            int r = rem >> 3, c = rem & 7;
            cp16(sbase + half * (BM * 128) + r * 128 + ((c ^ (r & 7)) << 4),
                 A + (size_t)(mBase + r) * Kr + half * K + kc * 64 + c * 8);
        }
        uint32_t bbase = sbase + 2 * BM * 128;
#pragma unroll
        for (int i = 0; i < BNUM; i++) {
            int idx = tid + i * NT;
            int half = idx >= BN * 8 ? 1 : 0;
            int rem = idx - half * BN * 8;
            int r = rem >> 3, c = rem & 7;
            cp16(bbase + half * (BN * 128) + r * 128 + ((c ^ (r & 7)) << 4),
                 B + (size_t)(nBase + r) * Kr + half * K + kc * 64 + c * 8);
        }
        cp_commit();
    };

    issue(0, 0);
    issue(1, 1);

    for (int kc = 0; kc < kIters; kc++) {
        int st = kc & 1;
        if (kc + 1 < kIters) cp_wait1(); else cp_wait0();
        __syncthreads();

        uint32_t aH = asB + st * SS;
        uint32_t aL = aH + BM * 128;
        uint32_t bH = aH + 2 * BM * 128;
        uint32_t bL = bH + BN * 128;

#pragma unroll
        for (int kk = 0; kk < 4; kk++) {
            uint32_t ofA = (((kk * 2 + cA) ^ s) << 4);
            uint32_t ofB = (((kk * 2 + cB) ^ s) << 4);
            uint32_t ahf[MI][4], alf[MI][4];
#pragma unroll
            for (int i = 0; i < MI; i++) {
                int row = rowA0 + i * 16;
                LDMX4(ahf[i][0], ahf[i][1], ahf[i][2], ahf[i][3], aH + row * 128 + ofA);
                LDMX4(alf[i][0], alf[i][1], alf[i][2], alf[i][3], aL + row * 128 + ofA);
            }
            uint32_t bhf[NLD][4], blf[NLD][4];
#pragma unroll
            for (int j = 0; j < NLD; j++) {
                int row = rowB0 + j * 16;
                LDMX4(bhf[j][0], bhf[j][1], bhf[j][2], bhf[j][3], bH + row * 128 + ofB);
                LDMX4(blf[j][0], blf[j][1], blf[j][2], blf[j][3], bL + row * 128 + ofB);
            }
#pragma unroll
            for (int i = 0; i < MI; i++)
#pragma unroll
                for (int j = 0; j < NJ; j++)
                    MMA16816(acc[i][j], ahf[i], bhf[j >> 1][(j & 1) * 2], bhf[j >> 1][(j & 1) * 2 + 1]);
#pragma unroll
            for (int i = 0; i < MI; i++)
#pragma unroll
                for (int j = 0; j < NJ; j++)
                    MMA16816(acc[i][j], alf[i], bhf[j >> 1][(j & 1) * 2], bhf[j >> 1][(j & 1) * 2 + 1]);
#pragma unroll
            for (int i = 0; i < MI; i++)
#pragma unroll
                for (int j = 0; j < NJ; j++)
                    MMA16816(acc[i][j], ahf[i], blf[j >> 1][(j & 1) * 2], blf[j >> 1][(j & 1) * 2 + 1]);
        }

        if (kc + 2 < kIters) {
            __syncthreads();            // all warps done reading slot st
            issue(kc + 2, st);
        }
    }

#pragma unroll
    for (int i = 0; i < MI; i++) {
        int row = mBase + wm * WM + i * 16 + (lane >> 2);
#pragma unroll
        for (int j = 0; j < NJ; j++) {
            int col = nBase + wn * WN + j * 8 + (lane & 3) * 2;
            *(float2*)(C + (size_t)row * N + col)       = make_float2(acc[i][j][0], acc[i][j][1]);
            *(float2*)(C + (size_t)(row + 8) * N + col) = make_float2(acc[i][j][2], acc[i][j][3]);
        }
    }

    if (done) {
        __threadfence();
        __syncthreads();
        if (tid == 0) atomicAdd(&done[blockIdx.y], 1u);
    }
}

// ============================================================================
// Single-pass hi-only GEMM (for q/k): C = Ah @ Bh^T.
// ============================================================================
template<int BM, int BN, int WM, int WN, int NT>
__global__ __launch_bounds__(NT, 2) void gemm1(
    const __nv_bfloat16* __restrict__ A, const __nv_bfloat16* __restrict__ B,
    float* __restrict__ C, int M, int N, int K)
{
    constexpr int NWN = BN / WN;
    constexpr int MI  = WM / 16;
    constexpr int NJ  = WN / 8;
    constexpr int NLD = WN / 16;
    constexpr int ANUM = BM * 8 / NT;
    constexpr int BNUM = BN * 8 / NT;
    constexpr int SS = BM * 128 + BN * 128;

    extern __shared__ __align__(16) unsigned char smem_raw[];
    uint32_t asB = (uint32_t)__cvta_generic_to_shared(smem_raw);

    const int tid  = threadIdx.x;
    const int lane = tid & 31;
    const int w    = tid >> 5;
    const int wm   = w / NWN, wn = w % NWN;
    const int mBase = blockIdx.y * BM;
    const int nBase = blockIdx.x * BN;
    const int Kr = 2 * K;

    float acc[MI][NJ][4];
#pragma unroll
    for (int i = 0; i < MI; i++)
#pragma unroll
        for (int j = 0; j < NJ; j++)
#pragma unroll
            for (int r = 0; r < 4; r++) acc[i][j][r] = 0.0f;

    const int s = lane & 7;
    const int rowA0 = wm * WM + (lane & 7) + ((lane >> 3) & 1) * 8;
    const int cA    = (lane >> 4);
    const int rowB0 = wn * WN + (lane & 7) + ((lane & 16) ? 8 : 0);
    const int cB    = (lane >> 3) & 1;

    const int kIters = K / 64;

    auto issue = [&](int kc, int st) {
        uint32_t sbase = asB + st * SS;
#pragma unroll
        for (int i = 0; i < ANUM; i++) {
            int idx = tid + i * NT;
            int r = idx >> 3, c = idx & 7;
            cp16(sbase + r * 128 + ((c ^ (r & 7)) << 4),
                 A + (size_t)(mBase + r) * Kr + kc * 64 + c * 8);
        }
        uint32_t bbase = sbase + BM * 128;
#pragma unroll
        for (int i = 0; i < BNUM; i++) {
            int idx = tid + i * NT;
            int r = idx >> 3, c = idx & 7;
            cp16(bbase + r * 128 + ((c ^ (r & 7)) << 4),
                 B + (size_t)(nBase + r) * Kr + kc * 64 + c * 8);
        }
        cp_commit();
    };

    issue(0, 0);
    issue(1, 1);

    for (int kc = 0; kc < kIters; kc++) {
        int st = kc & 1;
        if (kc + 1 < kIters) cp_wait1(); else cp_wait0();
        __syncthreads();

        uint32_t aH = asB + st * SS;
        uint32_t bH = aH + BM * 128;

#pragma unroll
        for (int kk = 0; kk < 4; kk++) {
            uint32_t ofA = (((kk * 2 + cA) ^ s) << 4);
            uint32_t ofB = (((kk * 2 + cB) ^ s) << 4);
            uint32_t ahf[MI][4];
#pragma unroll
            for (int i = 0; i < MI; i++) {
                int row = rowA0 + i * 16;
                LDMX4(ahf[i][0], ahf[i][1], ahf[i][2], ahf[i][3], aH + row * 128 + ofA);
            }
            uint32_t bhf[NLD][4];
#pragma unroll
            for (int j = 0; j < NLD; j++) {
                int row = rowB0 + j * 16;
                LDMX4(bhf[j][0], bhf[j][1], bhf[j][2], bhf[j][3], bH + row * 128 + ofB);
            }
#pragma unroll
            for (int i = 0; i < MI; i++)
#pragma unroll
                for (int j = 0; j < NJ; j++)
                    MMA16816(acc[i][j], ahf[i], bhf[j >> 1][(j & 1) * 2], bhf[j >> 1][(j & 1) * 2 + 1]);
        }

        if (kc + 2 < kIters) {
            __syncthreads();
            issue(kc + 2, st);
        }
    }

#pragma unroll
    for (int i = 0; i < MI; i++) {
        int row = mBase + wm * WM + i * 16 + (lane >> 2);
#pragma unroll
        for (int j = 0; j < NJ; j++) {
            int col = nBase + wn * WN + j * 8 + (lane & 3) * 2;
            *(float2*)(C + (size_t)row * N + col)       = make_float2(acc[i][j][0], acc[i][j][1]);
            *(float2*)(C + (size_t)(row + 8) * N + col) = make_float2(acc[i][j][2], acc[i][j][3]);
        }
    }
}

// ---------------- persistent LSTM (R10 config) + per-step xp-flag pacing -----
__global__ __launch_bounds__(256) void lstm_persistent(
    const __nv_bfloat16* __restrict__ Whhs, float* __restrict__ rnn_out)
{
    constexpr int BM = 64, BN = 64, WM = 32, WN = 16, NT = 256;
    constexpr int NWN = BN / WN;      // 4
    constexpr int MI = WM / 16;       // 2
    constexpr int NJ = WN / 8;        // 2
    constexpr int ANUM = BM * 16 / NT;// 4
    constexpr int BNUM = BN * 16 / NT;// 4
    constexpr int SS = 2 * BM * 128 + 2 * BN * 128;   // 32KB
    constexpr int NBLOCKS = 128;
    constexpr int K = 1024;
    constexpr unsigned XP_BLOCKS_PER_T = 64;

    extern __shared__ __align__(16) unsigned char smem_raw[];
    uint32_t asB = (uint32_t)__cvta_generic_to_shared(smem_raw);
    float* gsh = (float*)smem_raw;

    const int tid  = threadIdx.x;
    const int lane = tid & 31;
    const int w    = tid >> 5;
    const int wm   = w / NWN, wn = w % NWN;
    const int u0   = blockIdx.x * 16;
    const int b0   = blockIdx.y * 64;

    const int s = lane & 7;
    const int rowA0 = wm * WM + (lane & 7) + ((lane >> 3) & 1) * 8;
    const int cA    = (lane >> 4);
    const int rowB0 = wn * WN + (lane & 7) + ((lane & 16) ? 8 : 0);
    const int cB    = (lane >> 3) & 1;

    int aHalf[ANUM], aR[ANUM], aC[ANUM];
    int bHalf[BNUM], bGrow[BNUM], bR[BNUM], bC[BNUM];
#pragma unroll
    for (int i = 0; i < ANUM; i++) {
        int idx = tid + i * NT;
        aHalf[i] = idx >= BM * 8 ? 1 : 0;
        int rem = idx - aHalf[i] * BM * 8;
        aR[i] = rem >> 3; aC[i] = rem & 7;
    }
#pragma unroll
    for (int i = 0; i < BNUM; i++) {
        int idx = tid + i * NT;
        bHalf[i] = idx >= BN * 8 ? 1 : 0;
        int rem = idx - bHalf[i] * BN * 8;
        bR[i] = rem >> 3; bC[i] = rem & 7;
        bGrow[i] = (bR[i] >> 4) * HDIM + u0 + (bR[i] & 15);   // gate*H + u
    }

    unsigned bgen = 0;

    for (int t = 0; t < T_DEC; t++) {
        float acc[MI][NJ][4];
#pragma unroll
        for (int i = 0; i < MI; i++)
#pragma unroll
            for (int j = 0; j < NJ; j++)
#pragma unroll
                for (int r = 0; r < 4; r++) acc[i][j][r] = 0.0f;

        if (t > 0) {
            const __nv_bfloat16* hprev = g_rnns + (size_t)(t - 1) * BSZ * K2;
            auto issue = [&](int kc, int st) {
                uint32_t sbase = asB + st * SS;
#pragma unroll
                for (int i = 0; i < ANUM; i++)
                    cp16(sbase + aHalf[i] * (BM * 128) + aR[i] * 128 + ((aC[i] ^ (aR[i] & 7)) << 4),
                         hprev + (size_t)(b0 + aR[i]) * K2 + aHalf[i] * K + kc * 64 + aC[i] * 8);
                uint32_t bbase = sbase + 2 * BM * 128;
#pragma unroll
                for (int i = 0; i < BNUM; i++)
                    cp16(bbase + bHalf[i] * (BN * 128) + bR[i] * 128 + ((bC[i] ^ (bR[i] & 7)) << 4),
                         Whhs + (size_t)bGrow[i] * K2 + bHalf[i] * K + kc * 64 + bC[i] * 8);
                cp_commit();
            };

            issue(0, 0);
            issue(1, 1);

            const int kIters = K / 64;   // 16
            for (int kc = 0; kc < kIters; kc++) {
                int st = kc % 3;
                if (kc + 1 < kIters) cp_wait1(); else cp_wait0();
                __syncthreads();
                if (kc + 2 < kIters) issue(kc + 2, (kc + 2) % 3);

                uint32_t aH = asB + st * SS;
                uint32_t aL = aH + BM * 128;
                uint32_t bH = aH + 2 * BM * 128;
                uint32_t bL = bH + BN * 128;

#pragma unroll
                for (int kk = 0; kk < 4; kk++) {
                    uint32_t ofA = (((kk * 2 + cA) ^ s) << 4);
                    uint32_t ofB = (((kk * 2 + cB) ^ s) << 4);
                    uint32_t ahf[MI][4], alf[MI][4];
#pragma unroll
                    for (int i = 0; i < MI; i++) {
                        int row = rowA0 + i * 16;
                        LDMX4(ahf[i][0], ahf[i][1], ahf[i][2], ahf[i][3], aH + row * 128 + ofA);
                        LDMX4(alf[i][0], alf[i][1], alf[i][2], alf[i][3], aL + row * 128 + ofA);
                    }
                    uint32_t bhf[4], blf[4];
                    LDMX4(bhf[0], bhf[1], bhf[2], bhf[3], bH + rowB0 * 128 + ofB);
                    LDMX4(blf[0], blf[1], blf[2], blf[3], bL + rowB0 * 128 + ofB);
#pragma unroll
                    for (int i = 0; i < MI; i++)
#pragma unroll
                        for (int j = 0; j < NJ; j++)
                            MMA16816(acc[i][j], ahf[i], bhf[j * 2], bhf[j * 2 + 1]);
#pragma unroll
                    for (int i = 0; i < MI; i++)
#pragma unroll
                        for (int j = 0; j < NJ; j++)
                            MMA16816(acc[i][j], alf[i], bhf[j * 2], bhf[j * 2 + 1]);
#pragma unroll
                    for (int i = 0; i < MI; i++)
#pragma unroll
                        for (int j = 0; j < NJ; j++)
                            MMA16816(acc[i][j], ahf[i], blf[j * 2], blf[j * 2 + 1]);
                }
            }
            __syncthreads();   // all warps done reading stages before gsh aliases them
        } else {
            __syncthreads();
        }

        // stage gates in smem (aliases mainloop buffers)
#pragma unroll
        for (int i = 0; i < MI; i++) {
            int m = wm * WM + i * 16 + (lane >> 2);
#pragma unroll
            for (int j = 0; j < NJ; j++) {
                int col = wn * WN + j * 8 + (lane & 3) * 2;
                gsh[m * 65 + col]           = acc[i][j][0];
                gsh[m * 65 + col + 1]       = acc[i][j][1];
                gsh[(m + 8) * 65 + col]     = acc[i][j][2];
                gsh[(m + 8) * 65 + col + 1] = acc[i][j][3];
            }
        }
        __syncthreads();

        // wait for xp[t] (xp GEMM runs concurrently on another stream)
        if (tid == 0) {
            unsigned v;
            do {
                asm volatile("ld.acquire.gpu.u32 %0, [%1];"
                             : "=r"(v) : "l"(&g_xp_done[t]) : "memory");
                if (v < XP_BLOCKS_PER_T) __nanosleep(128);
            } while (v < XP_BLOCKS_PER_T);
        }
        __syncthreads();

        // fused cell update for the 64b x 16u tile
#pragma unroll
        for (int sIt = 0; sIt < 4; sIt++) {
            int idx = tid + sIt * 256;
            int bl = idx >> 4, uu = idx & 15;
            int b = b0 + bl, u = u0 + uu;
            size_t xb = ((size_t)t * BSZ + b) * G4 + u;
            float gi = gsh[bl * 65 + uu]      + g_bias[u]            + g_xp[xb];
            float gf = gsh[bl * 65 + 16 + uu] + g_bias[u + HDIM]     + g_xp[xb + HDIM];
            float gg = gsh[bl * 65 + 32 + uu] + g_bias[u + 2 * HDIM] + g_xp[xb + 2 * HDIM];
            float go = gsh[bl * 65 + 48 + uu] + g_bias[u + 3 * HDIM] + g_xp[xb + 3 * HDIM];
            float cp = g_c[(size_t)b * HDIM + u];
            float c  = sigm(gf) * cp + sigm(gi) * tanhf(gg);
            float h  = sigm(go) * tanhf(c);
            g_c[(size_t)b * HDIM + u] = c;
            rnn_out[((size_t)t * BSZ + b) * HDIM + u] = h;
            __nv_bfloat16 hh, hl; split2(h, hh, hl);
            size_t rb2 = ((size_t)t * BSZ + b) * K2;
            g_rnns[rb2 + u] = hh;
            g_rnns[rb2 + HDIM + u] = hl;
        }

        // device-wide barrier (skip after final step)
        if (t + 1 < T_DEC) {
            __syncthreads();
            if (tid == 0) {
                __threadfence();
                unsigned target = bgen + 1;
                if (atomicAdd(&g_bar_cnt, 1) == NBLOCKS - 1) {
                    g_bar_cnt = 0;
                    asm volatile("st.release.gpu.u32 [%0], %1;"
                                 :: "l"(&g_bar_gen), "r"(target) : "memory");
                } else {
                    unsigned v;
                    do {
                        __nanosleep(64);
                        asm volatile("ld.acquire.gpu.u32 %0, [%1];"
                                     : "=r"(v) : "l"(&g_bar_gen) : "memory");
                    } while (v < target);
                }
                bgen = target;
            }
            __syncthreads();
        }
    }
}

// ---------------- attention scores + masked softmax (8 tq/block, mask-skip) --
__global__ __launch_bounds__(256) void scores_kernel(const int* __restrict__ ctx_len,
                                                     const float* __restrict__ att_bias) {
    int tq0 = blockIdx.x * 8, b = blockIdx.y;
    __shared__ float qsh[8][HDIM];
    __shared__ float vnsh[HDIM];
    __shared__ float ssh[8][T_CTX];

    const int cl = ctx_len[b];

    for (int i = threadIdx.x; i < 8 * HDIM; i += 256) {
        int tqi = i >> 10, u = i & 1023;
        qsh[tqi][u] = g_q[((size_t)(tq0 + tqi) * BSZ + b) * HDIM + u] + att_bias[u];
    }
    for (int i = threadIdx.x; i < HDIM; i += 256) vnsh[i] = g_vn[i];
    __syncthreads();

    int w = threadIdx.x >> 5, lane = threadIdx.x & 31;
#pragma unroll
    for (int tkk = 0; tkk < 4; tkk++) {
        int tk = tkk * 8 + w;
        if (tk < cl) {
            const float* krow = g_k + ((size_t)tk * BSZ + b) * HDIM;
            float sacc[8];
#pragma unroll
            for (int qq = 0; qq < 8; qq++) sacc[qq] = 0.0f;
            for (int u = lane; u < HDIM; u += 32) {
                float kv = krow[u], vn = vnsh[u];
#pragma unroll
                for (int qq = 0; qq < 8; qq++)
                    sacc[qq] += tanh_fast(qsh[qq][u] + kv) * vn;
            }
#pragma unroll
            for (int qq = 0; qq < 8; qq++) {
#pragma unroll
                for (int off = 16; off > 0; off >>= 1)
                    sacc[qq] += __shfl_xor_sync(0xffffffffu, sacc[qq], off);
                if (lane == 0) ssh[qq][tk] = sacc[qq];
            }
        } else if (lane == 0) {
#pragma unroll
            for (int qq = 0; qq < 8; qq++) ssh[qq][tk] = -65504.0f;
        }
    }
    __syncthreads();

    {
        int tqi = threadIdx.x >> 5;   // 8 warps x 32 lanes = all 256 threads
        float s = ssh[tqi][lane];
        if (lane >= cl) s = -65504.0f;
        float m = s;
#pragma unroll
        for (int off = 16; off > 0; off >>= 1)
            m = fmaxf(m, __shfl_xor_sync(0xffffffffu, m, off));
        float e = __expf(s - m);
        float sum = e;
#pragma unroll
        for (int off = 16; off > 0; off >>= 1)
            sum += __shfl_xor_sync(0xffffffffu, sum, off);
        g_attn[((size_t)b * T_DEC + tq0 + tqi) * T_CTX + lane] = e / sum;
    }
}

// ---------------- attn_out: 16 tq/block; skip masked tk (attn exactly 0) ----
__global__ __launch_bounds__(256) void attnctx_kernel(
    const float* __restrict__ context, float* __restrict__ attn_out,
    const int* __restrict__ ctx_len)
{
    int tqh = blockIdx.x * 16, b = blockIdx.y;
    __shared__ float wsh[16][32];
#pragma unroll
    for (int it = 0; it < 2; it++) {
        int i = threadIdx.x + it * 256;
        if (i < 512) {
            int tq = i >> 5, tk = i & 31;
            wsh[tq][tk] = g_attn[((size_t)b * T_DEC + tqh + tq) * T_CTX + tk];
        }
    }
    __syncthreads();

    const int cl = ctx_len[b];
    int c4 = threadIdx.x;
    float acc[16][4];
#pragma unroll
    for (int tq = 0; tq < 16; tq++)
#pragma unroll
        for (int r = 0; r < 4; r++) acc[tq][r] = 0.0f;

#pragma unroll 4
    for (int tk = 0; tk < cl; tk++) {
        float4 v = *(const float4*)(context + ((size_t)tk * BSZ + b) * CDIM + c4 * 4);
#pragma unroll
        for (int tq = 0; tq < 16; tq++) {
            float wt = wsh[tq][tk];
            acc[tq][0] = fmaf(wt, v.x, acc[tq][0]);
            acc[tq][1] = fmaf(wt, v.y, acc[tq][1]);
            acc[tq][2] = fmaf(wt, v.z, acc[tq][2]);
            acc[tq][3] = fmaf(wt, v.w, acc[tq][3]);
        }
    }
#pragma unroll
    for (int tq = 0; tq < 16; tq++)
        *(float4*)(attn_out + ((size_t)(tqh + tq) * BSZ + b) * CDIM + c4 * 4) =
            make_float4(acc[tq][0], acc[tq][1], acc[tq][2], acc[tq][3]);
}

// ---------------- launcher ----------------
extern "C" void kernel_launch(void* const* d_in, const int* in_sizes, int n_in,
                              void* d_out, int out_size)
{
    const int*   ctx_len     = (const int*)  d_in[0];
    const int*   tokens      = (const int*)  d_in[1];
    const float* context     = (const float*)d_in[2];
    const float* emb_table   = (const float*)d_in[3];
    const float* W_ih        = (const float*)d_in[4];
    const float* W_hh        = (const float*)d_in[5];
    const float* b_ih        = (const float*)d_in[6];
    const float* b_hh        = (const float*)d_in[7];
    const float* Wq          = (const float*)d_in[8];
    const float* Wk          = (const float*)d_in[9];
    const float* v_att       = (const float*)d_in[10];
    const float* att_bias    = (const float*)d_in[11];
    const float* norm_scalar = (const float*)d_in[12];

    float* attn_out = (float*)d_out;
    float* rnn_out  = attn_out + (size_t)T_DEC * BSZ * CDIM;

    __nv_bfloat16 *p_embs, *p_Wihs, *p_Whhs, *p_Wqs, *p_Wks, *p_ctxs, *p_rnns;
    float *p_xp, *p_q, *p_k;
    unsigned* p_xpdone;
    cudaGetSymbolAddress((void**)&p_embs, g_embs);
    cudaGetSymbolAddress((void**)&p_Wihs, g_Wihs);
    cudaGetSymbolAddress((void**)&p_Whhs, g_Whhs);
    cudaGetSymbolAddress((void**)&p_Wqs,  g_Wqs);
    cudaGetSymbolAddress((void**)&p_Wks,  g_Wks);
    cudaGetSymbolAddress((void**)&p_ctxs, g_ctxs);
    cudaGetSymbolAddress((void**)&p_rnns, g_rnns);
    cudaGetSymbolAddress((void**)&p_xp,   g_xp);
    cudaGetSymbolAddress((void**)&p_q,    g_q);
    cudaGetSymbolAddress((void**)&p_k,    g_k);
    cudaGetSymbolAddress((void**)&p_xpdone, g_xp_done);

    static cudaStream_t s2 = nullptr, s3 = nullptr;
    static cudaEvent_t evFork = nullptr, evJoin = nullptr, evWhh = nullptr,
                       evInit = nullptr, evLstm = nullptr;
    if (!s2) {
        cudaStreamCreateWithFlags(&s2, cudaStreamNonBlocking);
        cudaStreamCreateWithFlags(&s3, cudaStreamNonBlocking);
        cudaEventCreateWithFlags(&evFork, cudaEventDisableTiming);
        cudaEventCreateWithFlags(&evJoin, cudaEventDisableTiming);
        cudaEventCreateWithFlags(&evWhh,  cudaEventDisableTiming);
        cudaEventCreateWithFlags(&evInit, cudaEventDisableTiming);
        cudaEventCreateWithFlags(&evLstm, cudaEventDisableTiming);
    }

    const int GEMM_SMEM = 2 * (2 * 128 * 128 + 2 * 64 * 128);   // 96KB -> 2 CTAs/SM
    cudaFuncSetAttribute(gemm3<128, 64, 32, 32, 256>,
                         cudaFuncAttributeMaxDynamicSharedMemorySize, GEMM_SMEM);
    const int GEMM1_SMEM = 2 * (128 * 128 + 64 * 128);          // 48KB -> 2 CTAs/SM
    cudaFuncSetAttribute(gemm1<128, 64, 32, 32, 256>,
                         cudaFuncAttributeMaxDynamicSharedMemorySize, GEMM1_SMEM);
    const int LSTM_SMEM = 3 * (2 * 64 * 128 + 2 * 64 * 128);    // 96KB
    cudaFuncSetAttribute(lstm_persistent,
                         cudaFuncAttributeMaxDynamicSharedMemorySize, LSTM_SMEM);

    // fork side stream s2 into capture
    cudaEventRecord(evFork, 0);
    cudaStreamWaitEvent(s2, evFork, 0);

    // ---- s2: W_hh split (LSTM dep) + k-projection path ----
    split2_kernel<<<(G4 * HDIM + 255) / 256, 256, 0, s2>>>(W_hh, p_Whhs, HDIM, G4 * HDIM);
    cudaEventRecord(evWhh, s2);
    split2_kernel<<<(HDIM * HDIM + 255) / 256, 256, 0, s2>>>(Wq, p_Wqs, HDIM, HDIM * HDIM);
    split2_kernel<<<(HDIM * CDIM + 255) / 256, 256, 0, s2>>>(Wk, p_Wks, CDIM, HDIM * CDIM);
    split2_kernel<<<(T_CTX * BSZ * CDIM + 255) / 256, 256, 0, s2>>>(
        context, p_ctxs, CDIM, T_CTX * BSZ * CDIM);
    gemm1<128, 64, 32, 32, 256>
        <<<dim3(HDIM / 64, (T_CTX * BSZ) / 128), 256, GEMM1_SMEM, s2>>>(
        p_ctxs, p_Wks, p_k, T_CTX * BSZ, HDIM, CDIM);
    cudaEventRecord(evJoin, s2);

    // ---- main stream: prep (only xp deps + init) ----
    init_kernel<<<(BSZ * HDIM + 255) / 256, 256>>>(b_ih, b_hh);
    cudaEventRecord(evInit, 0);
    vn_kernel<<<1, 256>>>(v_att, norm_scalar);
    embed_split<<<T_DEC * BSZ, 256>>>(tokens, emb_table);
    split2_kernel<<<(G4 * EDIM + 255) / 256, 256>>>(W_ih, p_Wihs, EDIM, G4 * EDIM);

    // ---- s3: persistent LSTM, self-paced on xp flags, CONCURRENT with xp ----
    cudaStreamWaitEvent(s3, evInit, 0);
    cudaStreamWaitEvent(s3, evWhh, 0);
    lstm_persistent<<<dim3(HDIM / 16, BSZ / 64), 256, LSTM_SMEM, s3>>>(p_Whhs, rnn_out);
    cudaEventRecord(evLstm, s3);

    // ---- main stream: xp GEMM with per-t completion flags ----
    gemm3<128, 64, 32, 32, 256>
        <<<dim3(G4 / 64, (T_DEC * BSZ) / 128), 256, GEMM_SMEM>>>(
        p_embs, p_Wihs, p_xp, T_DEC * BSZ, G4, EDIM, p_xpdone);

    // join LSTM + k-path, then q-projection (single-pass) + attention
    cudaStreamWaitEvent(0, evLstm, 0);
    cudaStreamWaitEvent(0, evJoin, 0);

    gemm1<128, 64, 32, 32, 256>
        <<<dim3(HDIM / 64, (T_DEC * BSZ) / 128), 256, GEMM1_SMEM>>>(
        p_rnns, p_Wqs, p_q, T_DEC * BSZ, HDIM, HDIM);

    scores_kernel<<<dim3(T_DEC / 8, BSZ), 256>>>(ctx_len, att_bias);
    attnctx_kernel<<<dim3(2, BSZ), 256>>>(context, attn_out, ctx_len);
}